// round 6
// baseline (speedup 1.0000x reference)
#include <cuda_runtime.h>
#include <math.h>

// Problem dims
#define NB 2
#define NS 2048
#define DM 1024
#define DK 64
#define NH 16

typedef unsigned long long ull;

// Packed fp32x2 ops (sm_103a): 2 fp32 FMAs per issue slot
#define FMA_F32X2(d, a, b, c) \
    asm("fma.rn.f32x2 %0, %1, %2, %3;" : "=l"(d) : "l"(a), "l"(b), "l"(c))
#define MUL_F32X2(d, a, b) \
    asm("mul.rn.f32x2 %0, %1, %2;" : "=l"(d) : "l"(a), "l"(b))

union F2 { ull u; float2 f; };

__device__ __forceinline__ ull pack2(float x, float y) {
    F2 t; t.f = make_float2(x, y); return t.u;
}

// Scratch (allocation-free rule: __device__ globals)
__device__ float g_Q[NB*NH*NS*DK];
__device__ float g_K[NB*NH*NS*DK];
__device__ float g_V[NB*NH*NS*DK];
__device__ float g_ctx[NB*NS*NH*DK];

// ---------------------------------------------------------------------------
// 64x64 tile GEMM core with FFMA2.
// As stored K-major and DUPLICATED along m: As[k][2m] = As[k][2m+1] = A[m][k]
// so the broadcast operand loads as ready-made (a,a) pairs via LDS.128.
// Bs normal [k][n]; n-pairs pack free from LDS.128.
// 256 threads, thread tile 4x4 (= 8 FFMA2/k-step), K-tile 32.
// ---------------------------------------------------------------------------
__device__ __forceinline__ void gemm64x64_core(
    const float* __restrict__ A, int lda,
    const float* __restrict__ Bm, int ldb,
    float* __restrict__ C, int ldc, int K)
{
    __shared__ __align__(16) float As[32][132];  // duplicated, 132 = align+bank pad
    __shared__ __align__(16) float Bs[32][64];
    const int tid = threadIdx.x;
    const int tx = tid & 15;   // n direction (x4)
    const int ty = tid >> 4;   // m direction (x4)

    ull acc2[4][2];
    #pragma unroll
    for (int i = 0; i < 4; i++) { acc2[i][0] = 0ULL; acc2[i][1] = 0ULL; }

    for (int k0 = 0; k0 < K; k0 += 32) {
        // Load A tile: 64 rows x 32 k = 512 float4, write duplicated pairs
        #pragma unroll
        for (int e = 0; e < 2; e++) {
            int idx = tid + e * 256;
            int r = idx >> 3, vc = idx & 7;
            float4 v = *(const float4*)(A + (size_t)r * lda + k0 + vc * 4);
            *(float2*)(&As[vc*4+0][2*r]) = make_float2(v.x, v.x);
            *(float2*)(&As[vc*4+1][2*r]) = make_float2(v.y, v.y);
            *(float2*)(&As[vc*4+2][2*r]) = make_float2(v.z, v.z);
            *(float2*)(&As[vc*4+3][2*r]) = make_float2(v.w, v.w);
        }
        // Load B tile: 32 rows x 64 cols = 512 float4
        #pragma unroll
        for (int e = 0; e < 2; e++) {
            int idx = tid + e * 256;
            int r = idx >> 4, vc = idx & 15;
            float4 v = *(const float4*)(Bm + (size_t)(k0 + r) * ldb + vc * 4);
            *(float4*)(&Bs[r][vc * 4]) = v;
        }
        __syncthreads();
        #pragma unroll
        for (int kk = 0; kk < 32; kk++) {
            // (a,a) broadcast pairs (2 LDS.128, broadcast across tx)
            ulonglong2 a01 = *(const ulonglong2*)(&As[kk][8 * ty]);
            ulonglong2 a23 = *(const ulonglong2*)(&As[kk][8 * ty + 4]);
            // (b,b') n-pairs (1 LDS.128)
            ulonglong2 b01 = *(const ulonglong2*)(&Bs[kk][4 * tx]);
            FMA_F32X2(acc2[0][0], a01.x, b01.x, acc2[0][0]);
            FMA_F32X2(acc2[0][1], a01.x, b01.y, acc2[0][1]);
            FMA_F32X2(acc2[1][0], a01.y, b01.x, acc2[1][0]);
            FMA_F32X2(acc2[1][1], a01.y, b01.y, acc2[1][1]);
            FMA_F32X2(acc2[2][0], a23.x, b01.x, acc2[2][0]);
            FMA_F32X2(acc2[2][1], a23.x, b01.y, acc2[2][1]);
            FMA_F32X2(acc2[3][0], a23.y, b01.x, acc2[3][0]);
            FMA_F32X2(acc2[3][1], a23.y, b01.y, acc2[3][1]);
        }
        __syncthreads();
    }
    #pragma unroll
    for (int i = 0; i < 4; i++) {
        F2 p0, p1; p0.u = acc2[i][0]; p1.u = acc2[i][1];
        float4 o = make_float4(p0.f.x, p0.f.y, p1.f.x, p1.f.y);
        *(float4*)(C + (size_t)(ty * 4 + i) * ldc + tx * 4) = o;
    }
}

// ---------------------------------------------------------------------------
// QKV projection: per block z = type*16 + h. out = x_b @ W[h], layout [B,H,S,DK]
// ---------------------------------------------------------------------------
__global__ void __launch_bounds__(256) qkv_proj_kernel(
    const float* __restrict__ x,
    const float* __restrict__ Wq,
    const float* __restrict__ Wk,
    const float* __restrict__ Wv)
{
    int m0 = blockIdx.x * 64;            // s-tile
    int b  = blockIdx.y;
    int z  = blockIdx.z;                 // 0..47
    int type = z >> 4;
    int h    = z & 15;

    const float* W;
    float* outb;
    if (type == 0)      { W = Wq; outb = g_Q; }
    else if (type == 1) { W = Wk; outb = g_K; }
    else                { W = Wv; outb = g_V; }
    W += (size_t)h * DM * DK;
    float* out = outb + ((size_t)(b * NH + h) * NS + m0) * DK;
    const float* A = x + (size_t)b * NS * DM + (size_t)m0 * DM;

    gemm64x64_core(A, DM, W, DK, out, DK, DM);
}

// ---------------------------------------------------------------------------
// Flash-style attention with FFMA2. grid (S/128, B*H). 128 thr, 1 thr = 1 row.
// q and acc live as packed f32x2; K/V pairs come straight from ulonglong2 LDS.
// ---------------------------------------------------------------------------
__global__ void __launch_bounds__(128, 3) attn_kernel()
{
    __shared__ __align__(16) float sK[64 * 64];
    __shared__ __align__(16) float sV[64 * 64];

    const int bh = blockIdx.y;           // b*16 + h
    const int b  = bh >> 4;
    const int h  = bh & 15;
    const int s  = blockIdx.x * 128 + threadIdx.x;

    const float* Qrow  = g_Q + ((size_t)bh * NS + s) * DK;
    const float* Kbase = g_K + (size_t)bh * NS * DK;
    const float* Vbase = g_V + (size_t)bh * NS * DK;

    const float scale = 0.125f;          // 1/sqrt(64)
    ull q2[32];
    #pragma unroll
    for (int i = 0; i < 16; i++) {
        float4 v = *(const float4*)(Qrow + i * 4);
        q2[2*i+0] = pack2(v.x * scale, v.y * scale);
        q2[2*i+1] = pack2(v.z * scale, v.w * scale);
    }

    ull acc2[32];
    #pragma unroll
    for (int i = 0; i < 32; i++) acc2[i] = 0ULL;
    float mmax = -INFINITY;
    float l = 0.0f;

    for (int jt = 0; jt < NS; jt += 64) {
        __syncthreads();
        const float4* gk = (const float4*)(Kbase + (size_t)jt * DK);
        const float4* gv = (const float4*)(Vbase + (size_t)jt * DK);
        #pragma unroll
        for (int e = 0; e < 8; e++) {
            int idx = threadIdx.x + e * 128;
            ((float4*)sK)[idx] = gk[idx];
            ((float4*)sV)[idx] = gv[idx];
        }
        __syncthreads();

        #pragma unroll 1
        for (int jc = 0; jc < 64; jc += 8) {
            float sc[8];
            #pragma unroll
            for (int j = 0; j < 8; j++) {
                const ulonglong2* kr = (const ulonglong2*)(sK + (jc + j) * DK);
                ull sA = 0ULL, sB = 0ULL, sC = 0ULL, sD = 0ULL;
                #pragma unroll
                for (int i = 0; i < 8; i++) {
                    ulonglong2 kv0 = kr[2 * i];
                    ulonglong2 kv1 = kr[2 * i + 1];
                    FMA_F32X2(sA, q2[4*i+0], kv0.x, sA);
                    FMA_F32X2(sB, q2[4*i+1], kv0.y, sB);
                    FMA_F32X2(sC, q2[4*i+2], kv1.x, sC);
                    FMA_F32X2(sD, q2[4*i+3], kv1.y, sD);
                }
                F2 ua, ub, uc, ud;
                ua.u = sA; ub.u = sB; uc.u = sC; ud.u = sD;
                sc[j] = ((ua.f.x + ua.f.y) + (ub.f.x + ub.f.y))
                      + ((uc.f.x + uc.f.y) + (ud.f.x + ud.f.y));
            }
            float tmax = sc[0];
            #pragma unroll
            for (int j = 1; j < 8; j++) tmax = fmaxf(tmax, sc[j]);
            if (tmax > mmax) {
                float corr = __expf(mmax - tmax);   // first time: exp(-inf)=0
                l *= corr;
                ull corr2 = pack2(corr, corr);
                #pragma unroll
                for (int i = 0; i < 32; i++) { MUL_F32X2(acc2[i], acc2[i], corr2); }
                mmax = tmax;
            }
            #pragma unroll
            for (int j = 0; j < 8; j++) {
                float p = __expf(sc[j] - mmax);
                l += p;
                ull p2 = pack2(p, p);
                const ulonglong2* vr = (const ulonglong2*)(sV + (jc + j) * DK);
                #pragma unroll
                for (int i = 0; i < 16; i++) {
                    ulonglong2 vv = vr[i];
                    FMA_F32X2(acc2[2*i+0], p2, vv.x, acc2[2*i+0]);
                    FMA_F32X2(acc2[2*i+1], p2, vv.y, acc2[2*i+1]);
                }
            }
        }
    }

    float inv = 1.0f / l;
    float* out = g_ctx + ((size_t)(b * NS + s)) * (NH * DK) + h * DK;
    #pragma unroll
    for (int i = 0; i < 16; i++) {
        F2 p0, p1; p0.u = acc2[2*i+0]; p1.u = acc2[2*i+1];
        float4 o = make_float4(p0.f.x * inv, p0.f.y * inv,
                               p1.f.x * inv, p1.f.y * inv);
        *(float4*)(out + 4 * i) = o;
    }
}

// ---------------------------------------------------------------------------
// Output projection: out[4096,1024] = ctx[4096,1024] @ Wo[1024,1024]
// ---------------------------------------------------------------------------
__global__ void __launch_bounds__(256) out_proj_kernel(
    const float* __restrict__ Wo, float* __restrict__ out)
{
    int n0 = blockIdx.x * 64;
    int m0 = blockIdx.y * 64;
    gemm64x64_core(g_ctx + (size_t)m0 * (NH * DK), NH * DK,
                   Wo + n0, DM,
                   out + (size_t)m0 * DM + n0, DM, NH * DK);
}

// ---------------------------------------------------------------------------
extern "C" void kernel_launch(void* const* d_in, const int* in_sizes, int n_in,
                              void* d_out, int out_size)
{
    (void)in_sizes; (void)n_in; (void)out_size;
    // metadata order: x, Wk, Wq, Wv, Wo
    const float* x  = (const float*)d_in[0];
    const float* Wk = (const float*)d_in[1];
    const float* Wq = (const float*)d_in[2];
    const float* Wv = (const float*)d_in[3];
    const float* Wo = (const float*)d_in[4];
    float* out = (float*)d_out;

    qkv_proj_kernel<<<dim3(NS / 64, NB, 48), 256>>>(x, Wq, Wk, Wv);
    attn_kernel<<<dim3(NS / 128, NB * NH), 128>>>();
    out_proj_kernel<<<dim3(DM / 64, (NB * NS) / 64), 256>>>(Wo, out);
}

// round 12
// speedup vs baseline: 1.6633x; 1.6633x over previous
#include <cuda_runtime.h>
#include <cuda_bf16.h>
#include <math.h>
#include <stdint.h>

#define NB 2
#define NS 2048
#define DM 1024
#define DK 64
#define NH 16
#define LDT 40   // padded smem row stride (elems) -> conflict-free ldmatrix

typedef unsigned int u32;
typedef __nv_bfloat16 bf16;

// ---------------- scratch (__device__ globals; no allocs allowed) ----------
__device__ float g_Q[NB*NH*NS*DK];
__device__ float g_K[NB*NH*NS*DK];
__device__ float g_V[NB*NH*NS*DK];
__device__ float g_ctx[NB*NS*NH*DK];
__device__ bf16 g_Xhi[NB*NS*DM];
__device__ bf16 g_Xlo[NB*NS*DM];
__device__ bf16 g_Wthi[NH*3*DK*DM];   // [h][p*64+n][m]  (p: 0=Q,1=K,2=V)
__device__ bf16 g_Wtlo[NH*3*DK*DM];
__device__ bf16 g_Wohi[DM*DM];        // [mo][c] = Wo[c][mo]
__device__ bf16 g_Wolo[DM*DM];
__device__ bf16 g_Chi[NB*NS*NH*DK];
__device__ bf16 g_Clo[NB*NS*NH*DK];

// ---------------- bf16 hi/lo split ----------------------------------------
__device__ __forceinline__ void split2(float x, bf16* hi, bf16* lo) {
    bf16 h = __float2bfloat16(x);
    *hi = h;
    *lo = __float2bfloat16(x - __bfloat162float(h));
}

__global__ void prep_x_kernel(const float* __restrict__ x) {
    int i = blockIdx.x * 256 + threadIdx.x;
    split2(x[i], &g_Xhi[i], &g_Xlo[i]);
}
__global__ void prep_w_kernel(const float* __restrict__ Wq,
                              const float* __restrict__ Wk,
                              const float* __restrict__ Wv) {
    int i = blockIdx.x * 256 + threadIdx.x;           // NH*192*DM
    int m  = i & (DM - 1);
    int t  = i >> 10;
    int pn = t % 192;
    int h  = t / 192;
    int p  = pn >> 6, n = pn & 63;
    const float* W = (p == 0) ? Wq : ((p == 1) ? Wk : Wv);
    float v = W[(size_t)h * DM * DK + (size_t)m * DK + n];
    split2(v, &g_Wthi[i], &g_Wtlo[i]);
}
__global__ void prep_wo_kernel(const float* __restrict__ Wo) {
    int i = blockIdx.x * 256 + threadIdx.x;           // DM*DM, i = mo*1024 + c
    int c = i & (DM - 1), mo = i >> 10;
    split2(Wo[(size_t)c * DM + mo], &g_Wohi[i], &g_Wolo[i]);
}
__global__ void prep_ctx_kernel() {
    int i = blockIdx.x * 256 + threadIdx.x;
    split2(g_ctx[i], &g_Chi[i], &g_Clo[i]);
}

// ---------------- warp MMA helpers (plain sm_80-era PTX, compute_103-legal) -
__device__ __forceinline__ u32 smem_u32(const void* p) {
    u32 a;
    asm("{ .reg .u64 t; cvta.to.shared.u64 t, %1; cvt.u32.u64 %0, t; }" : "=r"(a) : "l"(p));
    return a;
}
__device__ __forceinline__ void ldsm4(u32* r, u32 a) {
    asm volatile("ldmatrix.sync.aligned.m8n8.x4.shared.b16 {%0,%1,%2,%3}, [%4];"
                 : "=r"(r[0]), "=r"(r[1]), "=r"(r[2]), "=r"(r[3]) : "r"(a));
}
__device__ __forceinline__ void mma16816(float* c, const u32* a, const u32* b) {
    asm volatile(
        "mma.sync.aligned.m16n8k16.row.col.f32.bf16.bf16.f32 "
        "{%0,%1,%2,%3}, {%4,%5,%6,%7}, {%8,%9}, {%0,%1,%2,%3};"
        : "+f"(c[0]), "+f"(c[1]), "+f"(c[2]), "+f"(c[3])
        : "r"(a[0]), "r"(a[1]), "r"(a[2]), "r"(a[3]), "r"(b[0]), "r"(b[1]));
}

// ---------------------------------------------------------------------------
// Split-bf16 GEMM core: C[128x64] += A[128xDM] @ B[64xDM]^T  (B row-major [n][k])
// 256 threads, 8 warps (4 along M x 2 along N), warp tile 32x32, K-tile 32.
// C ~= Ahi Bhi + Ahi Blo + Alo Bhi  (fp32 accum) -> ~2^-15 rel error
// ---------------------------------------------------------------------------
__device__ __forceinline__ void gemm_mma_core(
    const bf16* __restrict__ Agh, const bf16* __restrict__ Agl,
    const bf16* __restrict__ Bgh, const bf16* __restrict__ Bgl,
    bf16* sAh, bf16* sAl, bf16* sBh, bf16* sBl,
    float C[8][4])
{
    const int tid  = threadIdx.x;
    const int lane = tid & 31, wid = tid >> 5;
    const int wy = wid >> 1, wx = wid & 1;
    const int quad = lane >> 3, qr = lane & 7;
    const int a_row = (quad & 1) * 8 + qr, a_col = (quad >> 1) * 8;
    const int b_row = (quad >> 1) * 8 + qr, b_col = (quad & 1) * 8;

    const u32 aAh = smem_u32(sAh), aAl = smem_u32(sAl);
    const u32 aBh = smem_u32(sBh), aBl = smem_u32(sBl);

    #pragma unroll
    for (int i = 0; i < 8; i++)
        #pragma unroll
        for (int j = 0; j < 4; j++) C[i][j] = 0.0f;

    for (int kt = 0; kt < DM; kt += 32) {
        // fill A (128x32 hi/lo): 512 16B-chunks each -> 2 per thread
        #pragma unroll
        for (int e = 0; e < 2; e++) {
            int idx = tid + e * 256;
            int r = idx >> 2, c = idx & 3;
            *(uint4*)(sAh + r * LDT + c * 8) =
                *(const uint4*)(Agh + (size_t)r * DM + kt + c * 8);
            *(uint4*)(sAl + r * LDT + c * 8) =
                *(const uint4*)(Agl + (size_t)r * DM + kt + c * 8);
        }
        // fill B (64x32 hi/lo): 256 chunks each -> 1 per thread
        {
            int r = tid >> 2, c = tid & 3;
            *(uint4*)(sBh + r * LDT + c * 8) =
                *(const uint4*)(Bgh + (size_t)r * DM + kt + c * 8);
            *(uint4*)(sBl + r * LDT + c * 8) =
                *(const uint4*)(Bgl + (size_t)r * DM + kt + c * 8);
        }
        __syncthreads();

        #pragma unroll
        for (int k16 = 0; k16 < 2; k16++) {
            u32 Afh[2][4], Afl[2][4], Bfh[2][4], Bfl[2][4];
            #pragma unroll
            for (int mi = 0; mi < 2; mi++) {
                int row = wy * 32 + mi * 16 + a_row;
                u32 off = (u32)(row * LDT + k16 * 16 + a_col) * 2;
                ldsm4(Afh[mi], aAh + off);
                ldsm4(Afl[mi], aAl + off);
            }
            #pragma unroll
            for (int ng = 0; ng < 2; ng++) {
                int row = wx * 32 + ng * 16 + b_row;
                u32 off = (u32)(row * LDT + k16 * 16 + b_col) * 2;
                ldsm4(Bfh[ng], aBh + off);
                ldsm4(Bfl[ng], aBl + off);
            }
            #pragma unroll
            for (int mi = 0; mi < 2; mi++)
                #pragma unroll
                for (int ng = 0; ng < 2; ng++)
                    #pragma unroll
                    for (int hf = 0; hf < 2; hf++) {
                        float* c = C[mi * 4 + ng * 2 + hf];
                        mma16816(c, Afh[mi], &Bfh[ng][hf * 2]);
                        mma16816(c, Afh[mi], &Bfl[ng][hf * 2]);
                        mma16816(c, Afl[mi], &Bfh[ng][hf * 2]);
                    }
        }
        __syncthreads();
    }
}

// ---------------- QKV projection ------------------------------------------
__global__ void __launch_bounds__(256) qkv_mma_kernel() {
    __shared__ __align__(16) bf16 sAh[128 * LDT], sAl[128 * LDT];
    __shared__ __align__(16) bf16 sBh[64 * LDT],  sBl[64 * LDT];

    const int m0 = blockIdx.x * 128;
    const int h  = blockIdx.y;
    const int p  = blockIdx.z;

    float C[8][4];
    gemm_mma_core(g_Xhi + (size_t)m0 * DM, g_Xlo + (size_t)m0 * DM,
                  g_Wthi + ((size_t)h * 192 + p * 64) * DM,
                  g_Wtlo + ((size_t)h * 192 + p * 64) * DM,
                  sAh, sAl, sBh, sBl, C);

    float* dst = (p == 0) ? g_Q : ((p == 1) ? g_K : g_V);
    const int lane = threadIdx.x & 31, wid = threadIdx.x >> 5;
    const int wy = wid >> 1, wx = wid & 1;
    const int g = lane >> 2, t = lane & 3;
    #pragma unroll
    for (int mi = 0; mi < 2; mi++)
        #pragma unroll
        for (int n8 = 0; n8 < 4; n8++) {
            const float* c = C[mi * 4 + n8];
            int gm = m0 + wy * 32 + mi * 16 + g;
            int n  = wx * 32 + n8 * 8 + t * 2;
            int b = gm >> 11, s = gm & (NS - 1);
            float* o = dst + ((size_t)(b * NH + h) * NS + s) * DK + n;
            *(float2*)o = make_float2(c[0], c[1]);
            *(float2*)(o + 8 * DK) = make_float2(c[2], c[3]);
        }
}

// ---------------- output projection ----------------------------------------
__global__ void __launch_bounds__(256) out_mma_kernel(float* __restrict__ out) {
    __shared__ __align__(16) bf16 sAh[128 * LDT], sAl[128 * LDT];
    __shared__ __align__(16) bf16 sBh[64 * LDT],  sBl[64 * LDT];

    const int n0 = blockIdx.x * 64;
    const int m0 = blockIdx.y * 128;

    float C[8][4];
    gemm_mma_core(g_Chi + (size_t)m0 * DM, g_Clo + (size_t)m0 * DM,
                  g_Wohi + (size_t)n0 * DM, g_Wolo + (size_t)n0 * DM,
                  sAh, sAl, sBh, sBl, C);

    const int lane = threadIdx.x & 31, wid = threadIdx.x >> 5;
    const int wy = wid >> 1, wx = wid & 1;
    const int g = lane >> 2, t = lane & 3;
    #pragma unroll
    for (int mi = 0; mi < 2; mi++)
        #pragma unroll
        for (int n8 = 0; n8 < 4; n8++) {
            const float* c = C[mi * 4 + n8];
            int gm = m0 + wy * 32 + mi * 16 + g;
            int n  = n0 + wx * 32 + n8 * 8 + t * 2;
            float* o = out + (size_t)gm * DM + n;
            *(float2*)o = make_float2(c[0], c[1]);
            *(float2*)(o + 8 * DM) = make_float2(c[2], c[3]);
        }
}

// ---------------- fp32 flash attention (R1, at fp32 roofline) ---------------
__global__ void __launch_bounds__(128, 3) attn_kernel() {
    __shared__ __align__(16) float sK[64 * 64];
    __shared__ __align__(16) float sV[64 * 64];

    const int bh = blockIdx.y;
    const int b  = bh >> 4;
    const int h  = bh & 15;
    const int s  = blockIdx.x * 128 + threadIdx.x;

    const float* Qrow  = g_Q + ((size_t)bh * NS + s) * DK;
    const float* Kbase = g_K + (size_t)bh * NS * DK;
    const float* Vbase = g_V + (size_t)bh * NS * DK;

    const float scale = 0.125f;
    float q[DK];
    #pragma unroll
    for (int i = 0; i < 16; i++) {
        float4 v = *(const float4*)(Qrow + i * 4);
        q[4*i+0] = v.x * scale; q[4*i+1] = v.y * scale;
        q[4*i+2] = v.z * scale; q[4*i+3] = v.w * scale;
    }

    float acc[DK];
    #pragma unroll
    for (int i = 0; i < DK; i++) acc[i] = 0.0f;
    float mmax = -INFINITY;
    float l = 0.0f;

    for (int jt = 0; jt < NS; jt += 64) {
        __syncthreads();
        const float4* gk = (const float4*)(Kbase + (size_t)jt * DK);
        const float4* gv = (const float4*)(Vbase + (size_t)jt * DK);
        #pragma unroll
        for (int e = 0; e < 8; e++) {
            int idx = threadIdx.x + e * 128;
            ((float4*)sK)[idx] = gk[idx];
            ((float4*)sV)[idx] = gv[idx];
        }
        __syncthreads();

        #pragma unroll 1
        for (int jc = 0; jc < 64; jc += 8) {
            float sc[8];
            #pragma unroll
            for (int j = 0; j < 8; j++) {
                const float* kr = sK + (jc + j) * DK;
                float s0 = 0.f, s1 = 0.f, s2 = 0.f, s3 = 0.f;
                #pragma unroll
                for (int i = 0; i < DK; i += 4) {
                    float4 kv = *(const float4*)(kr + i);
                    s0 = fmaf(q[i + 0], kv.x, s0);
                    s1 = fmaf(q[i + 1], kv.y, s1);
                    s2 = fmaf(q[i + 2], kv.z, s2);
                    s3 = fmaf(q[i + 3], kv.w, s3);
                }
                sc[j] = (s0 + s1) + (s2 + s3);
            }
            float tmax = sc[0];
            #pragma unroll
            for (int j = 1; j < 8; j++) tmax = fmaxf(tmax, sc[j]);
            if (tmax > mmax) {
                float corr = __expf(mmax - tmax);
                l *= corr;
                #pragma unroll
                for (int i = 0; i < DK; i++) acc[i] *= corr;
                mmax = tmax;
            }
            #pragma unroll
            for (int j = 0; j < 8; j++) {
                float p = __expf(sc[j] - mmax);
                l += p;
                const float* vr = sV + (jc + j) * DK;
                #pragma unroll
                for (int i = 0; i < DK; i += 4) {
                    float4 vv = *(const float4*)(vr + i);
                    acc[i + 0] = fmaf(p, vv.x, acc[i + 0]);
                    acc[i + 1] = fmaf(p, vv.y, acc[i + 1]);
                    acc[i + 2] = fmaf(p, vv.z, acc[i + 2]);
                    acc[i + 3] = fmaf(p, vv.w, acc[i + 3]);
                }
            }
        }
    }

    float inv = 1.0f / l;
    float* o = g_ctx + ((size_t)(b * NS + s)) * (NH * DK) + h * DK;
    #pragma unroll
    for (int i = 0; i < 16; i++) {
        float4 v = make_float4(acc[4*i+0]*inv, acc[4*i+1]*inv,
                               acc[4*i+2]*inv, acc[4*i+3]*inv);
        *(float4*)(o + 4 * i) = v;
    }
}

// ---------------------------------------------------------------------------
extern "C" void kernel_launch(void* const* d_in, const int* in_sizes, int n_in,
                              void* d_out, int out_size)
{
    (void)in_sizes; (void)n_in; (void)out_size;
    // metadata order: x, Wk, Wq, Wv, Wo
    const float* x  = (const float*)d_in[0];
    const float* Wk = (const float*)d_in[1];
    const float* Wq = (const float*)d_in[2];
    const float* Wv = (const float*)d_in[3];
    const float* Wo = (const float*)d_in[4];
    float* out = (float*)d_out;

    prep_x_kernel<<<(NB*NS*DM)/256, 256>>>(x);
    prep_w_kernel<<<(NH*3*DK*DM)/256, 256>>>(Wq, Wk, Wv);
    prep_wo_kernel<<<(DM*DM)/256, 256>>>(Wo);
    qkv_mma_kernel<<<dim3(32, NH, 3), 256>>>();
    attn_kernel<<<dim3(NS/128, NB*NH), 128>>>();
    prep_ctx_kernel<<<(NB*NS*NH*DK)/256, 256>>>();
    out_mma_kernel<<<dim3(DM/64, (NB*NS)/128), 256>>>(out);
}

// round 14
// speedup vs baseline: 3.7706x; 2.2669x over previous
#include <cuda_runtime.h>
#include <cuda_bf16.h>
#include <math.h>
#include <stdint.h>

#define NB 2
#define NS 2048
#define DM 1024
#define DK 64
#define NH 16
#define LDT 40   // padded smem row stride (elems) for 32-wide GEMM tiles
#define ALD 72   // padded smem row stride (elems) for 64-wide attention tiles

typedef unsigned int u32;
typedef __nv_bfloat16 bf16;

// ---------------- scratch (__device__ globals; no allocs allowed) ----------
__device__ bf16 g_Qhi[NB*NH*NS*DK];  // Q pre-scaled by 1/8
__device__ bf16 g_Qlo[NB*NH*NS*DK];
__device__ bf16 g_Khi[NB*NH*NS*DK];
__device__ bf16 g_Klo[NB*NH*NS*DK];
__device__ bf16 g_Vhi[NB*NH*NS*DK];
__device__ bf16 g_Vlo[NB*NH*NS*DK];
__device__ bf16 g_Xhi[NB*NS*DM];
__device__ bf16 g_Xlo[NB*NS*DM];
__device__ bf16 g_Wthi[NH*3*DK*DM];   // [h][p*64+n][m]  (p: 0=Q,1=K,2=V)
__device__ bf16 g_Wtlo[NH*3*DK*DM];
__device__ bf16 g_Wohi[DM*DM];        // [mo][c] = Wo[c][mo]
__device__ bf16 g_Wolo[DM*DM];
__device__ bf16 g_Chi[NB*NS*NH*DK];   // ctx split, [b*NS+s][h*64+n]
__device__ bf16 g_Clo[NB*NS*NH*DK];

// ---------------- bf16 hi/lo split ----------------------------------------
__device__ __forceinline__ void split2(float x, bf16* hi, bf16* lo) {
    bf16 h = __float2bfloat16(x);
    *hi = h;
    *lo = __float2bfloat16(x - __bfloat162float(h));
}
// split a pair into packed bf16x2 hi and lo words (low half = first element)
__device__ __forceinline__ void pack_pair(float x, float y, u32& hi, u32& lo) {
    __nv_bfloat162 h = __floats2bfloat162_rn(x, y);
    hi = *(u32*)&h;
    float rx = x - __bfloat162float(h.x);
    float ry = y - __bfloat162float(h.y);
    __nv_bfloat162 l2 = __floats2bfloat162_rn(rx, ry);
    lo = *(u32*)&l2;
}

__global__ void prep_x_kernel(const float* __restrict__ x) {
    int i = blockIdx.x * 256 + threadIdx.x;
    split2(x[i], &g_Xhi[i], &g_Xlo[i]);
}
__global__ void prep_w_kernel(const float* __restrict__ Wq,
                              const float* __restrict__ Wk,
                              const float* __restrict__ Wv) {
    int i = blockIdx.x * 256 + threadIdx.x;           // NH*192*DM
    int m  = i & (DM - 1);
    int t  = i >> 10;
    int pn = t % 192;
    int h  = t / 192;
    int p  = pn >> 6, n = pn & 63;
    const float* W = (p == 0) ? Wq : ((p == 1) ? Wk : Wv);
    float v = W[(size_t)h * DM * DK + (size_t)m * DK + n];
    split2(v, &g_Wthi[i], &g_Wtlo[i]);
}
__global__ void prep_wo_kernel(const float* __restrict__ Wo) {
    int i = blockIdx.x * 256 + threadIdx.x;           // DM*DM, i = mo*1024 + c
    int c = i & (DM - 1), mo = i >> 10;
    split2(Wo[(size_t)c * DM + mo], &g_Wohi[i], &g_Wolo[i]);
}

// ---------------- warp MMA helpers -----------------------------------------
__device__ __forceinline__ u32 smem_u32(const void* p) {
    u32 a;
    asm("{ .reg .u64 t; cvta.to.shared.u64 t, %1; cvt.u32.u64 %0, t; }" : "=r"(a) : "l"(p));
    return a;
}
__device__ __forceinline__ void ldsm4(u32* r, u32 a) {
    asm volatile("ldmatrix.sync.aligned.m8n8.x4.shared.b16 {%0,%1,%2,%3}, [%4];"
                 : "=r"(r[0]), "=r"(r[1]), "=r"(r[2]), "=r"(r[3]) : "r"(a));
}
__device__ __forceinline__ void ldsm4t(u32* r, u32 a) {
    asm volatile("ldmatrix.sync.aligned.m8n8.x4.trans.shared.b16 {%0,%1,%2,%3}, [%4];"
                 : "=r"(r[0]), "=r"(r[1]), "=r"(r[2]), "=r"(r[3]) : "r"(a));
}
__device__ __forceinline__ void mma16816(float* c, const u32* a, const u32* b) {
    asm volatile(
        "mma.sync.aligned.m16n8k16.row.col.f32.bf16.bf16.f32 "
        "{%0,%1,%2,%3}, {%4,%5,%6,%7}, {%8,%9}, {%0,%1,%2,%3};"
        : "+f"(c[0]), "+f"(c[1]), "+f"(c[2]), "+f"(c[3])
        : "r"(a[0]), "r"(a[1]), "r"(a[2]), "r"(a[3]), "r"(b[0]), "r"(b[1]));
}

// ---------------------------------------------------------------------------
// Split-bf16 GEMM core (unchanged from R12): C[128x64] = A[128xDM] @ B[64xDM]^T
// ---------------------------------------------------------------------------
__device__ __forceinline__ void gemm_mma_core(
    const bf16* __restrict__ Agh, const bf16* __restrict__ Agl,
    const bf16* __restrict__ Bgh, const bf16* __restrict__ Bgl,
    bf16* sAh, bf16* sAl, bf16* sBh, bf16* sBl,
    float C[8][4])
{
    const int tid  = threadIdx.x;
    const int lane = tid & 31, wid = tid >> 5;
    const int wy = wid >> 1, wx = wid & 1;
    const int quad = lane >> 3, qr = lane & 7;
    const int a_row = (quad & 1) * 8 + qr, a_col = (quad >> 1) * 8;
    const int b_row = (quad >> 1) * 8 + qr, b_col = (quad & 1) * 8;

    const u32 aAh = smem_u32(sAh), aAl = smem_u32(sAl);
    const u32 aBh = smem_u32(sBh), aBl = smem_u32(sBl);

    #pragma unroll
    for (int i = 0; i < 8; i++)
        #pragma unroll
        for (int j = 0; j < 4; j++) C[i][j] = 0.0f;

    for (int kt = 0; kt < DM; kt += 32) {
        #pragma unroll
        for (int e = 0; e < 2; e++) {
            int idx = tid + e * 256;
            int r = idx >> 2, c = idx & 3;
            *(uint4*)(sAh + r * LDT + c * 8) =
                *(const uint4*)(Agh + (size_t)r * DM + kt + c * 8);
            *(uint4*)(sAl + r * LDT + c * 8) =
                *(const uint4*)(Agl + (size_t)r * DM + kt + c * 8);
        }
        {
            int r = tid >> 2, c = tid & 3;
            *(uint4*)(sBh + r * LDT + c * 8) =
                *(const uint4*)(Bgh + (size_t)r * DM + kt + c * 8);
            *(uint4*)(sBl + r * LDT + c * 8) =
                *(const uint4*)(Bgl + (size_t)r * DM + kt + c * 8);
        }
        __syncthreads();

        #pragma unroll
        for (int k16 = 0; k16 < 2; k16++) {
            u32 Afh[2][4], Afl[2][4], Bfh[2][4], Bfl[2][4];
            #pragma unroll
            for (int mi = 0; mi < 2; mi++) {
                int row = wy * 32 + mi * 16 + a_row;
                u32 off = (u32)(row * LDT + k16 * 16 + a_col) * 2;
                ldsm4(Afh[mi], aAh + off);
                ldsm4(Afl[mi], aAl + off);
            }
            #pragma unroll
            for (int ng = 0; ng < 2; ng++) {
                int row = wx * 32 + ng * 16 + b_row;
                u32 off = (u32)(row * LDT + k16 * 16 + b_col) * 2;
                ldsm4(Bfh[ng], aBh + off);
                ldsm4(Bfl[ng], aBl + off);
            }
            #pragma unroll
            for (int mi = 0; mi < 2; mi++)
                #pragma unroll
                for (int ng = 0; ng < 2; ng++)
                    #pragma unroll
                    for (int hf = 0; hf < 2; hf++) {
                        float* c = C[mi * 4 + ng * 2 + hf];
                        mma16816(c, Afh[mi], &Bfh[ng][hf * 2]);
                        mma16816(c, Afh[mi], &Bfl[ng][hf * 2]);
                        mma16816(c, Afl[mi], &Bfh[ng][hf * 2]);
                    }
        }
        __syncthreads();
    }
}

// ---------------- QKV projection: epilogue emits split bf16 Q/K/V -----------
__global__ void __launch_bounds__(256) qkv_mma_kernel() {
    __shared__ __align__(16) bf16 sAh[128 * LDT], sAl[128 * LDT];
    __shared__ __align__(16) bf16 sBh[64 * LDT],  sBl[64 * LDT];

    const int m0 = blockIdx.x * 128;
    const int h  = blockIdx.y;
    const int p  = blockIdx.z;

    float C[8][4];
    gemm_mma_core(g_Xhi + (size_t)m0 * DM, g_Xlo + (size_t)m0 * DM,
                  g_Wthi + ((size_t)h * 192 + p * 64) * DM,
                  g_Wtlo + ((size_t)h * 192 + p * 64) * DM,
                  sAh, sAl, sBh, sBl, C);

    bf16 *dh, *dl;
    float sc;
    if (p == 0)      { dh = g_Qhi; dl = g_Qlo; sc = 0.125f; }
    else if (p == 1) { dh = g_Khi; dl = g_Klo; sc = 1.0f; }
    else             { dh = g_Vhi; dl = g_Vlo; sc = 1.0f; }

    const int lane = threadIdx.x & 31, wid = threadIdx.x >> 5;
    const int wy = wid >> 1, wx = wid & 1;
    const int g = lane >> 2, t = lane & 3;
    #pragma unroll
    for (int mi = 0; mi < 2; mi++)
        #pragma unroll
        for (int n8 = 0; n8 < 4; n8++) {
            const float* c = C[mi * 4 + n8];
            int gm = m0 + wy * 32 + mi * 16 + g;
            int n  = wx * 32 + n8 * 8 + t * 2;
            int b = gm >> 11, s = gm & (NS - 1);
            size_t base = ((size_t)(b * NH + h) * NS + s) * DK + n;
            u32 hi, lo;
            pack_pair(c[0] * sc, c[1] * sc, hi, lo);
            *(u32*)(dh + base) = hi; *(u32*)(dl + base) = lo;
            pack_pair(c[2] * sc, c[3] * sc, hi, lo);
            *(u32*)(dh + base + 8 * DK) = hi; *(u32*)(dl + base + 8 * DK) = lo;
        }
}

// ---------------- HMMA flash attention --------------------------------------
// grid (S/128, B*H), 256 threads (8 warps x 16 q-rows). Key tiles of 64.
// scores: 3-term split MMA; online softmax on C-frags; PV: 3-term split MMA.
__global__ void __launch_bounds__(256, 2) attn_mma_kernel() {
    extern __shared__ __align__(16) bf16 dsm[];
    bf16* sQh = dsm;                  // 128*ALD
    bf16* sQl = sQh + 128 * ALD;
    bf16* sKh = sQl + 128 * ALD;      // 64*ALD each below
    bf16* sKl = sKh + 64 * ALD;
    bf16* sVh = sKl + 64 * ALD;
    bf16* sVl = sVh + 64 * ALD;

    const int tid = threadIdx.x, lane = tid & 31, wid = tid >> 5;
    const int bh = blockIdx.y, b = bh >> 4, h = bh & 15;
    const int m0 = blockIdx.x * 128;
    const int g = lane >> 2, t = lane & 3;
    const int quad = lane >> 3, qr = lane & 7;

    const bf16* gQh = g_Qhi + ((size_t)bh * NS + m0) * DK;
    const bf16* gQl = g_Qlo + ((size_t)bh * NS + m0) * DK;
    const bf16* gKh = g_Khi + (size_t)bh * NS * DK;
    const bf16* gKl = g_Klo + (size_t)bh * NS * DK;
    const bf16* gVh = g_Vhi + (size_t)bh * NS * DK;
    const bf16* gVl = g_Vlo + (size_t)bh * NS * DK;

    // fill Q tiles (128 rows x 64): 1024 chunks per buffer
    #pragma unroll
    for (int e = 0; e < 8; e++) {
        int idx = tid + e * 256;                    // 0..2047
        int buf = idx >> 10, sub = idx & 1023;
        int r = sub >> 3, c = sub & 7;
        const bf16* src = (buf == 0 ? gQh : gQl) + (size_t)r * DK + c * 8;
        bf16* dst = (buf == 0 ? sQh : sQl) + r * ALD + c * 8;
        *(uint4*)dst = *(const uint4*)src;
    }

    const u32 aQh = smem_u32(sQh), aQl = smem_u32(sQl);
    const u32 aKh = smem_u32(sKh), aKl = smem_u32(sKl);
    const u32 aVh = smem_u32(sVh), aVl = smem_u32(sVl);

    const int a_row  = wid * 16 + (quad & 1) * 8 + qr;  // Q frag row
    const int a_colb = (quad >> 1) * 8;
    const int kb_row  = (quad >> 1) * 8 + qr;           // K frag row (+np*16)
    const int kb_colb = (quad & 1) * 8;
    const int vb_row  = (quad & 1) * 8 + qr;            // V trans row (+k16*16)
    const int vb_colb = (quad >> 1) * 8;

    float O[8][4];
    #pragma unroll
    for (int i = 0; i < 8; i++)
        #pragma unroll
        for (int j = 0; j < 4; j++) O[i][j] = 0.0f;
    float m0r = -INFINITY, m1r = -INFINITY, l0 = 0.0f, l1 = 0.0f;

    for (int tile = 0; tile < NS / 64; tile++) {
        // fill K/V tiles (4 buffers x 512 chunks)
        #pragma unroll
        for (int e = 0; e < 8; e++) {
            int idx = tid + e * 256;                // 0..2047
            int buf = idx >> 9, sub = idx & 511;
            int r = sub >> 3, c = sub & 7;
            const bf16* src;
            bf16* dst;
            if (buf == 0)      { src = gKh; dst = sKh; }
            else if (buf == 1) { src = gKl; dst = sKl; }
            else if (buf == 2) { src = gVh; dst = sVh; }
            else               { src = gVl; dst = sVl; }
            *(uint4*)(dst + r * ALD + c * 8) =
                *(const uint4*)(src + (size_t)(tile * 64 + r) * DK + c * 8);
        }
        __syncthreads();

        // ---- scores S[16 x 64] per warp ----
        float S[8][4];
        #pragma unroll
        for (int i = 0; i < 8; i++)
            #pragma unroll
            for (int j = 0; j < 4; j++) S[i][j] = 0.0f;

        #pragma unroll
        for (int k16 = 0; k16 < 4; k16++) {
            u32 qh[4], ql[4];
            u32 qoff = (u32)(a_row * ALD + k16 * 16 + a_colb) * 2;
            ldsm4(qh, aQh + qoff);
            ldsm4(ql, aQl + qoff);
            #pragma unroll
            for (int np = 0; np < 4; np++) {
                u32 koff = (u32)((np * 16 + kb_row) * ALD + k16 * 16 + kb_colb) * 2;
                u32 kh[4], kl[4];
                ldsm4(kh, aKh + koff);
                ldsm4(kl, aKl + koff);
                #pragma unroll
                for (int hf = 0; hf < 2; hf++) {
                    float* c = S[np * 2 + hf];
                    mma16816(c, qh, &kh[hf * 2]);
                    mma16816(c, qh, &kl[hf * 2]);
                    mma16816(c, ql, &kh[hf * 2]);
                }
            }
        }

        // ---- online softmax on C-frags ----
        float mx0 = S[0][0], mx1 = S[0][2];
        #pragma unroll
        for (int i = 0; i < 8; i++) {
            mx0 = fmaxf(mx0, fmaxf(S[i][0], S[i][1]));
            mx1 = fmaxf(mx1, fmaxf(S[i][2], S[i][3]));
        }
        mx0 = fmaxf(mx0, __shfl_xor_sync(0xffffffffu, mx0, 1));
        mx0 = fmaxf(mx0, __shfl_xor_sync(0xffffffffu, mx0, 2));
        mx1 = fmaxf(mx1, __shfl_xor_sync(0xffffffffu, mx1, 1));
        mx1 = fmaxf(mx1, __shfl_xor_sync(0xffffffffu, mx1, 2));
        float mn0 = fmaxf(m0r, mx0), mn1 = fmaxf(m1r, mx1);
        float c0 = __expf(m0r - mn0), c1 = __expf(m1r - mn1);
        m0r = mn0; m1r = mn1;
        float s0 = 0.0f, s1 = 0.0f;
        #pragma unroll
        for (int i = 0; i < 8; i++) {
            S[i][0] = __expf(S[i][0] - m0r); s0 += S[i][0];
            S[i][1] = __expf(S[i][1] - m0r); s0 += S[i][1];
            S[i][2] = __expf(S[i][2] - m1r); s1 += S[i][2];
            S[i][3] = __expf(S[i][3] - m1r); s1 += S[i][3];
            O[i][0] *= c0; O[i][1] *= c0;
            O[i][2] *= c1; O[i][3] *= c1;
        }
        s0 += __shfl_xor_sync(0xffffffffu, s0, 1);
        s0 += __shfl_xor_sync(0xffffffffu, s0, 2);
        s1 += __shfl_xor_sync(0xffffffffu, s1, 1);
        s1 += __shfl_xor_sync(0xffffffffu, s1, 2);
        l0 = l0 * c0 + s0;
        l1 = l1 * c1 + s1;

        // ---- PV: O += P @ V ----
        #pragma unroll
        for (int k16 = 0; k16 < 4; k16++) {
            u32 ah[4], al[4];
            pack_pair(S[2*k16][0],   S[2*k16][1],   ah[0], al[0]);
            pack_pair(S[2*k16][2],   S[2*k16][3],   ah[1], al[1]);
            pack_pair(S[2*k16+1][0], S[2*k16+1][1], ah[2], al[2]);
            pack_pair(S[2*k16+1][2], S[2*k16+1][3], ah[3], al[3]);
            #pragma unroll
            for (int np = 0; np < 4; np++) {
                u32 voff = (u32)((k16 * 16 + vb_row) * ALD + np * 16 + vb_colb) * 2;
                u32 vh[4], vl[4];
                ldsm4t(vh, aVh + voff);
                ldsm4t(vl, aVl + voff);
                #pragma unroll
                for (int hf = 0; hf < 2; hf++) {
                    float* o = O[np * 2 + hf];
                    mma16816(o, ah, &vh[hf * 2]);
                    mma16816(o, ah, &vl[hf * 2]);
                    mma16816(o, al, &vh[hf * 2]);
                }
            }
        }
        __syncthreads();
    }

    // ---- epilogue: O/l -> split ctx ----
    float inv0 = 1.0f / l0, inv1 = 1.0f / l1;
    int srow = m0 + wid * 16 + g;
    #pragma unroll
    for (int n8 = 0; n8 < 8; n8++) {
        int n = h * 64 + n8 * 8 + t * 2;
        size_t r0 = (size_t)(b * NS + srow) * (NH * DK) + n;
        size_t r1 = r0 + (size_t)8 * NH * DK;
        u32 hi, lo;
        pack_pair(O[n8][0] * inv0, O[n8][1] * inv0, hi, lo);
        *(u32*)(g_Chi + r0) = hi; *(u32*)(g_Clo + r0) = lo;
        pack_pair(O[n8][2] * inv1, O[n8][3] * inv1, hi, lo);
        *(u32*)(g_Chi + r1) = hi; *(u32*)(g_Clo + r1) = lo;
    }
}

// ---------------- output projection ----------------------------------------
__global__ void __launch_bounds__(256) out_mma_kernel(float* __restrict__ out) {
    __shared__ __align__(16) bf16 sAh[128 * LDT], sAl[128 * LDT];
    __shared__ __align__(16) bf16 sBh[64 * LDT],  sBl[64 * LDT];

    const int n0 = blockIdx.x * 64;
    const int m0 = blockIdx.y * 128;

    float C[8][4];
    gemm_mma_core(g_Chi + (size_t)m0 * DM, g_Clo + (size_t)m0 * DM,
                  g_Wohi + (size_t)n0 * DM, g_Wolo + (size_t)n0 * DM,
                  sAh, sAl, sBh, sBl, C);

    const int lane = threadIdx.x & 31, wid = threadIdx.x >> 5;
    const int wy = wid >> 1, wx = wid & 1;
    const int g = lane >> 2, t = lane & 3;
    #pragma unroll
    for (int mi = 0; mi < 2; mi++)
        #pragma unroll
        for (int n8 = 0; n8 < 4; n8++) {
            const float* c = C[mi * 4 + n8];
            int gm = m0 + wy * 32 + mi * 16 + g;
            int n  = n0 + wx * 32 + n8 * 8 + t * 2;
            float* o = out + (size_t)gm * DM + n;
            *(float2*)o = make_float2(c[0], c[1]);
            *(float2*)(o + 8 * DM) = make_float2(c[2], c[3]);
        }
}

// ---------------------------------------------------------------------------
extern "C" void kernel_launch(void* const* d_in, const int* in_sizes, int n_in,
                              void* d_out, int out_size)
{
    (void)in_sizes; (void)n_in; (void)out_size;
    // metadata order: x, Wk, Wq, Wv, Wo
    const float* x  = (const float*)d_in[0];
    const float* Wk = (const float*)d_in[1];
    const float* Wq = (const float*)d_in[2];
    const float* Wv = (const float*)d_in[3];
    const float* Wo = (const float*)d_in[4];
    float* out = (float*)d_out;

    const int ATT_SMEM = (128 * 2 + 64 * 4) * ALD * sizeof(bf16);   // 73728 B
    cudaFuncSetAttribute(attn_mma_kernel,
                         cudaFuncAttributeMaxDynamicSharedMemorySize, ATT_SMEM);

    prep_x_kernel<<<(NB*NS*DM)/256, 256>>>(x);
    prep_w_kernel<<<(NH*3*DK*DM)/256, 256>>>(Wq, Wk, Wv);
    prep_wo_kernel<<<(DM*DM)/256, 256>>>(Wo);
    qkv_mma_kernel<<<dim3(32, NH, 3), 256>>>();
    attn_mma_kernel<<<dim3(NS/128, NB*NH), 256, ATT_SMEM>>>();
    out_mma_kernel<<<dim3(DM/64, (NB*NS)/128), 256>>>(out);
}

// round 16
// speedup vs baseline: 3.9669x; 1.0520x over previous
#include <cuda_runtime.h>
#include <cuda_bf16.h>
#include <math.h>
#include <stdint.h>

#define NB 2
#define NS 2048
#define DM 1024
#define DK 64
#define NH 16
#define LDT 40   // padded smem row stride (elems) for 32-wide GEMM tiles
#define ALD 72   // padded smem row stride (elems) for 64-wide attention tiles

typedef unsigned int u32;
typedef __nv_bfloat16 bf16;

// ---------------- scratch (__device__ globals; no allocs allowed) ----------
__device__ bf16 g_Qhi[NB*NH*NS*DK];  // Q pre-scaled by 1/8
__device__ bf16 g_Qlo[NB*NH*NS*DK];
__device__ bf16 g_Khi[NB*NH*NS*DK];
__device__ bf16 g_Klo[NB*NH*NS*DK];
__device__ bf16 g_Vhi[NB*NH*NS*DK];
__device__ bf16 g_Vlo[NB*NH*NS*DK];
__device__ bf16 g_Xhi[NB*NS*DM];
__device__ bf16 g_Xlo[NB*NS*DM];
__device__ bf16 g_Wthi[NH*3*DK*DM];   // [h][p*64+n][m]  (p: 0=Q,1=K,2=V)
__device__ bf16 g_Wtlo[NH*3*DK*DM];
__device__ bf16 g_Wohi[DM*DM];        // [mo][c] = Wo[c][mo]
__device__ bf16 g_Wolo[DM*DM];
__device__ bf16 g_Chi[NB*NS*NH*DK];   // ctx split, [b*NS+s][h*64+n]
__device__ bf16 g_Clo[NB*NS*NH*DK];

// ---------------- bf16 hi/lo split ----------------------------------------
__device__ __forceinline__ void split2(float x, bf16* hi, bf16* lo) {
    bf16 h = __float2bfloat16(x);
    *hi = h;
    *lo = __float2bfloat16(x - __bfloat162float(h));
}
__device__ __forceinline__ void pack_pair(float x, float y, u32& hi, u32& lo) {
    __nv_bfloat162 h = __floats2bfloat162_rn(x, y);
    hi = *(u32*)&h;
    float rx = x - __bfloat162float(h.x);
    float ry = y - __bfloat162float(h.y);
    __nv_bfloat162 l2 = __floats2bfloat162_rn(rx, ry);
    lo = *(u32*)&l2;
}

__global__ void prep_x_kernel(const float* __restrict__ x) {
    int i = blockIdx.x * 256 + threadIdx.x;
    split2(x[i], &g_Xhi[i], &g_Xlo[i]);
}
__global__ void prep_w_kernel(const float* __restrict__ Wq,
                              const float* __restrict__ Wk,
                              const float* __restrict__ Wv) {
    int i = blockIdx.x * 256 + threadIdx.x;           // NH*192*DM
    int m  = i & (DM - 1);
    int t  = i >> 10;
    int pn = t % 192;
    int h  = t / 192;
    int p  = pn >> 6, n = pn & 63;
    const float* W = (p == 0) ? Wq : ((p == 1) ? Wk : Wv);
    float v = W[(size_t)h * DM * DK + (size_t)m * DK + n];
    split2(v, &g_Wthi[i], &g_Wtlo[i]);
}
__global__ void prep_wo_kernel(const float* __restrict__ Wo) {
    int i = blockIdx.x * 256 + threadIdx.x;           // DM*DM, i = mo*1024 + c
    int c = i & (DM - 1), mo = i >> 10;
    split2(Wo[(size_t)c * DM + mo], &g_Wohi[i], &g_Wolo[i]);
}

// ---------------- PTX helpers -----------------------------------------------
__device__ __forceinline__ u32 smem_u32(const void* p) {
    u32 a;
    asm("{ .reg .u64 t; cvta.to.shared.u64 t, %1; cvt.u32.u64 %0, t; }" : "=r"(a) : "l"(p));
    return a;
}
__device__ __forceinline__ void cpa16(u32 dst, const void* src) {
    asm volatile("cp.async.ca.shared.global [%0], [%1], 16;" :: "r"(dst), "l"(src));
}
#define CP_COMMIT() asm volatile("cp.async.commit_group;" ::: "memory")
#define CP_WAIT(n)  asm volatile("cp.async.wait_group %0;" :: "n"(n) : "memory")
__device__ __forceinline__ void ldsm4(u32* r, u32 a) {
    asm volatile("ldmatrix.sync.aligned.m8n8.x4.shared.b16 {%0,%1,%2,%3}, [%4];"
                 : "=r"(r[0]), "=r"(r[1]), "=r"(r[2]), "=r"(r[3]) : "r"(a));
}
__device__ __forceinline__ void ldsm4t(u32* r, u32 a) {
    asm volatile("ldmatrix.sync.aligned.m8n8.x4.trans.shared.b16 {%0,%1,%2,%3}, [%4];"
                 : "=r"(r[0]), "=r"(r[1]), "=r"(r[2]), "=r"(r[3]) : "r"(a));
}
__device__ __forceinline__ void mma16816(float* c, const u32* a, const u32* b) {
    asm volatile(
        "mma.sync.aligned.m16n8k16.row.col.f32.bf16.bf16.f32 "
        "{%0,%1,%2,%3}, {%4,%5,%6,%7}, {%8,%9}, {%0,%1,%2,%3};"
        : "+f"(c[0]), "+f"(c[1]), "+f"(c[2]), "+f"(c[3])
        : "r"(a[0]), "r"(a[1]), "r"(a[2]), "r"(a[3]), "r"(b[0]), "r"(b[1]));
}

// ---------------------------------------------------------------------------
// Split-bf16 GEMM core, 2-stage cp.async pipeline.
// C[128x64] = A[128xDM] @ B[64xDM]^T (B row-major [n][k])
// Dynamic smem: stage s at: A hi/lo 128*LDT each, B hi/lo 64*LDT each.
// ---------------------------------------------------------------------------
#define G_AH(s) ((s) * 30720u)
#define G_AL(s) (G_AH(s) + 10240u)
#define G_BH(s) (G_AH(s) + 20480u)
#define G_BL(s) (G_AH(s) + 25600u)
#define GEMM_SMEM 61440

__device__ __forceinline__ void gemm_fill(
    u32 sb, int s,
    const bf16* __restrict__ Agh, const bf16* __restrict__ Agl,
    const bf16* __restrict__ Bgh, const bf16* __restrict__ Bgl,
    int kt, int tid)
{
    #pragma unroll
    for (int e = 0; e < 2; e++) {
        int idx = tid + e * 256;
        int r = idx >> 2, c = idx & 3;
        u32 off = (u32)(r * LDT + c * 8) * 2;
        cpa16(sb + G_AH(s) + off, Agh + (size_t)r * DM + kt + c * 8);
        cpa16(sb + G_AL(s) + off, Agl + (size_t)r * DM + kt + c * 8);
    }
    {
        int r = tid >> 2, c = tid & 3;
        u32 off = (u32)(r * LDT + c * 8) * 2;
        cpa16(sb + G_BH(s) + off, Bgh + (size_t)r * DM + kt + c * 8);
        cpa16(sb + G_BL(s) + off, Bgl + (size_t)r * DM + kt + c * 8);
    }
}

__device__ __forceinline__ void gemm_mma_core(
    const bf16* __restrict__ Agh, const bf16* __restrict__ Agl,
    const bf16* __restrict__ Bgh, const bf16* __restrict__ Bgl,
    u32 sb, float C[8][4])
{
    const int tid  = threadIdx.x;
    const int lane = tid & 31, wid = tid >> 5;
    const int wy = wid >> 1, wx = wid & 1;
    const int quad = lane >> 3, qr = lane & 7;
    const int a_row = (quad & 1) * 8 + qr, a_col = (quad >> 1) * 8;
    const int b_row = (quad >> 1) * 8 + qr, b_col = (quad & 1) * 8;

    #pragma unroll
    for (int i = 0; i < 8; i++)
        #pragma unroll
        for (int j = 0; j < 4; j++) C[i][j] = 0.0f;

    gemm_fill(sb, 0, Agh, Agl, Bgh, Bgl, 0, tid);
    CP_COMMIT();

    #pragma unroll 1
    for (int it = 0; it < DM / 32; it++) {
        int cur = it & 1;
        if (it + 1 < DM / 32) {
            gemm_fill(sb, cur ^ 1, Agh, Agl, Bgh, Bgl, (it + 1) * 32, tid);
            CP_COMMIT();
            CP_WAIT(1);
        } else {
            CP_WAIT(0);
        }
        __syncthreads();

        const u32 aAh = sb + G_AH(cur), aAl = sb + G_AL(cur);
        const u32 aBh = sb + G_BH(cur), aBl = sb + G_BL(cur);
        #pragma unroll
        for (int k16 = 0; k16 < 2; k16++) {
            u32 Afh[2][4], Afl[2][4], Bfh[2][4], Bfl[2][4];
            #pragma unroll
            for (int mi = 0; mi < 2; mi++) {
                int row = wy * 32 + mi * 16 + a_row;
                u32 off = (u32)(row * LDT + k16 * 16 + a_col) * 2;
                ldsm4(Afh[mi], aAh + off);
                ldsm4(Afl[mi], aAl + off);
            }
            #pragma unroll
            for (int ng = 0; ng < 2; ng++) {
                int row = wx * 32 + ng * 16 + b_row;
                u32 off = (u32)(row * LDT + k16 * 16 + b_col) * 2;
                ldsm4(Bfh[ng], aBh + off);
                ldsm4(Bfl[ng], aBl + off);
            }
            #pragma unroll
            for (int mi = 0; mi < 2; mi++)
                #pragma unroll
                for (int ng = 0; ng < 2; ng++)
                    #pragma unroll
                    for (int hf = 0; hf < 2; hf++) {
                        float* c = C[mi * 4 + ng * 2 + hf];
                        mma16816(c, Afh[mi], &Bfh[ng][hf * 2]);
                        mma16816(c, Afh[mi], &Bfl[ng][hf * 2]);
                        mma16816(c, Afl[mi], &Bfh[ng][hf * 2]);
                    }
        }
        __syncthreads();
    }
}

// ---------------- QKV projection: epilogue emits split bf16 Q/K/V -----------
__global__ void __launch_bounds__(256) qkv_mma_kernel() {
    extern __shared__ __align__(16) char gsm[];
    u32 sb = smem_u32(gsm);

    const int m0 = blockIdx.x * 128;
    const int h  = blockIdx.y;
    const int p  = blockIdx.z;

    float C[8][4];
    gemm_mma_core(g_Xhi + (size_t)m0 * DM, g_Xlo + (size_t)m0 * DM,
                  g_Wthi + ((size_t)h * 192 + p * 64) * DM,
                  g_Wtlo + ((size_t)h * 192 + p * 64) * DM,
                  sb, C);

    bf16 *dh, *dl;
    float sc;
    if (p == 0)      { dh = g_Qhi; dl = g_Qlo; sc = 0.125f; }
    else if (p == 1) { dh = g_Khi; dl = g_Klo; sc = 1.0f; }
    else             { dh = g_Vhi; dl = g_Vlo; sc = 1.0f; }

    const int lane = threadIdx.x & 31, wid = threadIdx.x >> 5;
    const int wy = wid >> 1, wx = wid & 1;
    const int g = lane >> 2, t = lane & 3;
    #pragma unroll
    for (int mi = 0; mi < 2; mi++)
        #pragma unroll
        for (int n8 = 0; n8 < 4; n8++) {
            const float* c = C[mi * 4 + n8];
            int gm = m0 + wy * 32 + mi * 16 + g;
            int n  = wx * 32 + n8 * 8 + t * 2;
            int b = gm >> 11, s = gm & (NS - 1);
            size_t base = ((size_t)(b * NH + h) * NS + s) * DK + n;
            u32 hi, lo;
            pack_pair(c[0] * sc, c[1] * sc, hi, lo);
            *(u32*)(dh + base) = hi; *(u32*)(dl + base) = lo;
            pack_pair(c[2] * sc, c[3] * sc, hi, lo);
            *(u32*)(dh + base + 8 * DK) = hi; *(u32*)(dl + base + 8 * DK) = lo;
        }
}

// ---------------- HMMA flash attention with cp.async KV pipeline ------------
// Smem layout: Q hi/lo at 0 (2 x 128*ALD*2 = 36864), then 2 stages of
// {Kh,Kl,Vh,Vl} each 64*ALD*2 = 9216 -> stage stride 36864. Total 110592.
#define A_Q   0u
#define A_KV(s)    (36864u + (s) * 36864u)
#define A_BUF(s,b) (A_KV(s) + (b) * 9216u)
#define ATT_SMEM 110592

__global__ void __launch_bounds__(256, 2) attn_mma_kernel() {
    extern __shared__ __align__(16) char asm_[];
    u32 sb = smem_u32(asm_);

    const int tid = threadIdx.x, lane = tid & 31, wid = tid >> 5;
    const int bh = blockIdx.y, b = bh >> 4, h = bh & 15;
    const int m0 = blockIdx.x * 128;
    const int g = lane >> 2, t = lane & 3;
    const int quad = lane >> 3, qr = lane & 7;

    const bf16* gQh = g_Qhi + ((size_t)bh * NS + m0) * DK;
    const bf16* gQl = g_Qlo + ((size_t)bh * NS + m0) * DK;
    const bf16* gKh = g_Khi + (size_t)bh * NS * DK;
    const bf16* gKl = g_Klo + (size_t)bh * NS * DK;
    const bf16* gVh = g_Vhi + (size_t)bh * NS * DK;
    const bf16* gVl = g_Vlo + (size_t)bh * NS * DK;

    // Q tiles via cp.async (group 0 content; waits below cover it)
    #pragma unroll
    for (int e = 0; e < 8; e++) {
        int idx = tid + e * 256;                    // 0..2047
        int buf = idx >> 10, sub = idx & 1023;
        int r = sub >> 3, c = sub & 7;
        const bf16* src = (buf == 0 ? gQh : gQl) + (size_t)r * DK + c * 8;
        cpa16(sb + A_Q + (u32)(buf * 18432) + (u32)(r * ALD + c * 8) * 2, src);
    }
    // KV stage 0, tile 0
    #pragma unroll
    for (int e = 0; e < 8; e++) {
        int idx = tid + e * 256;
        int buf = idx >> 9, sub = idx & 511;
        int r = sub >> 3, c = sub & 7;
        const bf16* base = (buf == 0 ? gKh : buf == 1 ? gKl : buf == 2 ? gVh : gVl);
        cpa16(sb + A_BUF(0, buf) + (u32)(r * ALD + c * 8) * 2,
              base + (size_t)r * DK + c * 8);
    }
    CP_COMMIT();

    const int a_row  = wid * 16 + (quad & 1) * 8 + qr;  // Q frag row
    const int a_colb = (quad >> 1) * 8;
    const int kb_row  = (quad >> 1) * 8 + qr;           // K frag row (+np*16)
    const int kb_colb = (quad & 1) * 8;
    const int vb_row  = (quad & 1) * 8 + qr;            // V trans row (+k16*16)
    const int vb_colb = (quad >> 1) * 8;

    float O[8][4];
    #pragma unroll
    for (int i = 0; i < 8; i++)
        #pragma unroll
        for (int j = 0; j < 4; j++) O[i][j] = 0.0f;
    float m0r = -INFINITY, m1r = -INFINITY, l0 = 0.0f, l1 = 0.0f;

    #pragma unroll 1
    for (int tile = 0; tile < NS / 64; tile++) {
        int cur = tile & 1;
        if (tile + 1 < NS / 64) {
            #pragma unroll
            for (int e = 0; e < 8; e++) {
                int idx = tid + e * 256;
                int buf = idx >> 9, sub = idx & 511;
                int r = sub >> 3, c = sub & 7;
                const bf16* base = (buf == 0 ? gKh : buf == 1 ? gKl : buf == 2 ? gVh : gVl);
                cpa16(sb + A_BUF(cur ^ 1, buf) + (u32)(r * ALD + c * 8) * 2,
                      base + (size_t)((tile + 1) * 64 + r) * DK + c * 8);
            }
            CP_COMMIT();
            CP_WAIT(1);
        } else {
            CP_WAIT(0);
        }
        __syncthreads();

        const u32 aQh = sb + A_Q, aQl = sb + A_Q + 18432u;
        const u32 aKh = sb + A_BUF(cur, 0), aKl = sb + A_BUF(cur, 1);
        const u32 aVh = sb + A_BUF(cur, 2), aVl = sb + A_BUF(cur, 3);

        // ---- scores S[16 x 64] per warp ----
        float S[8][4];
        #pragma unroll
        for (int i = 0; i < 8; i++)
            #pragma unroll
            for (int j = 0; j < 4; j++) S[i][j] = 0.0f;

        #pragma unroll
        for (int k16 = 0; k16 < 4; k16++) {
            u32 qh[4], ql[4];
            u32 qoff = (u32)(a_row * ALD + k16 * 16 + a_colb) * 2;
            ldsm4(qh, aQh + qoff);
            ldsm4(ql, aQl + qoff);
            #pragma unroll
            for (int np = 0; np < 4; np++) {
                u32 koff = (u32)((np * 16 + kb_row) * ALD + k16 * 16 + kb_colb) * 2;
                u32 kh[4], kl[4];
                ldsm4(kh, aKh + koff);
                ldsm4(kl, aKl + koff);
                #pragma unroll
                for (int hf = 0; hf < 2; hf++) {
                    float* c = S[np * 2 + hf];
                    mma16816(c, qh, &kh[hf * 2]);
                    mma16816(c, qh, &kl[hf * 2]);
                    mma16816(c, ql, &kh[hf * 2]);
                }
            }
        }

        // ---- online softmax on C-frags ----
        float mx0 = S[0][0], mx1 = S[0][2];
        #pragma unroll
        for (int i = 0; i < 8; i++) {
            mx0 = fmaxf(mx0, fmaxf(S[i][0], S[i][1]));
            mx1 = fmaxf(mx1, fmaxf(S[i][2], S[i][3]));
        }
        mx0 = fmaxf(mx0, __shfl_xor_sync(0xffffffffu, mx0, 1));
        mx0 = fmaxf(mx0, __shfl_xor_sync(0xffffffffu, mx0, 2));
        mx1 = fmaxf(mx1, __shfl_xor_sync(0xffffffffu, mx1, 1));
        mx1 = fmaxf(mx1, __shfl_xor_sync(0xffffffffu, mx1, 2));
        float mn0 = fmaxf(m0r, mx0), mn1 = fmaxf(m1r, mx1);
        float c0 = __expf(m0r - mn0), c1 = __expf(m1r - mn1);
        m0r = mn0; m1r = mn1;
        float s0 = 0.0f, s1 = 0.0f;
        #pragma unroll
        for (int i = 0; i < 8; i++) {
            S[i][0] = __expf(S[i][0] - m0r); s0 += S[i][0];
            S[i][1] = __expf(S[i][1] - m0r); s0 += S[i][1];
            S[i][2] = __expf(S[i][2] - m1r); s1 += S[i][2];
            S[i][3] = __expf(S[i][3] - m1r); s1 += S[i][3];
            O[i][0] *= c0; O[i][1] *= c0;
            O[i][2] *= c1; O[i][3] *= c1;
        }
        s0 += __shfl_xor_sync(0xffffffffu, s0, 1);
        s0 += __shfl_xor_sync(0xffffffffu, s0, 2);
        s1 += __shfl_xor_sync(0xffffffffu, s1, 1);
        s1 += __shfl_xor_sync(0xffffffffu, s1, 2);
        l0 = l0 * c0 + s0;
        l1 = l1 * c1 + s1;

        // ---- PV: O += P @ V ----
        #pragma unroll
        for (int k16 = 0; k16 < 4; k16++) {
            u32 ah[4], al[4];
            pack_pair(S[2*k16][0],   S[2*k16][1],   ah[0], al[0]);
            pack_pair(S[2*k16][2],   S[2*k16][3],   ah[1], al[1]);
            pack_pair(S[2*k16+1][0], S[2*k16+1][1], ah[2], al[2]);
            pack_pair(S[2*k16+1][2], S[2*k16+1][3], ah[3], al[3]);
            #pragma unroll
            for (int np = 0; np < 4; np++) {
                u32 voff = (u32)((k16 * 16 + vb_row) * ALD + np * 16 + vb_colb) * 2;
                u32 vh[4], vl[4];
                ldsm4t(vh, aVh + voff);
                ldsm4t(vl, aVl + voff);
                #pragma unroll
                for (int hf = 0; hf < 2; hf++) {
                    float* o = O[np * 2 + hf];
                    mma16816(o, ah, &vh[hf * 2]);
                    mma16816(o, ah, &vl[hf * 2]);
                    mma16816(o, al, &vh[hf * 2]);
                }
            }
        }
        __syncthreads();
    }

    // ---- epilogue: O/l -> split ctx ----
    float inv0 = 1.0f / l0, inv1 = 1.0f / l1;
    int srow = m0 + wid * 16 + g;
    #pragma unroll
    for (int n8 = 0; n8 < 8; n8++) {
        int n = h * 64 + n8 * 8 + t * 2;
        size_t r0 = (size_t)(b * NS + srow) * (NH * DK) + n;
        size_t r1 = r0 + (size_t)8 * NH * DK;
        u32 hi, lo;
        pack_pair(O[n8][0] * inv0, O[n8][1] * inv0, hi, lo);
        *(u32*)(g_Chi + r0) = hi; *(u32*)(g_Clo + r0) = lo;
        pack_pair(O[n8][2] * inv1, O[n8][3] * inv1, hi, lo);
        *(u32*)(g_Chi + r1) = hi; *(u32*)(g_Clo + r1) = lo;
    }
}

// ---------------- output projection ----------------------------------------
__global__ void __launch_bounds__(256) out_mma_kernel(float* __restrict__ out) {
    extern __shared__ __align__(16) char gsm[];
    u32 sb = smem_u32(gsm);

    const int n0 = blockIdx.x * 64;
    const int m0 = blockIdx.y * 128;

    float C[8][4];
    gemm_mma_core(g_Chi + (size_t)m0 * DM, g_Clo + (size_t)m0 * DM,
                  g_Wohi + (size_t)n0 * DM, g_Wolo + (size_t)n0 * DM,
                  sb, C);

    const int lane = threadIdx.x & 31, wid = threadIdx.x >> 5;
    const int wy = wid >> 1, wx = wid & 1;
    const int g = lane >> 2, t = lane & 3;
    #pragma unroll
    for (int mi = 0; mi < 2; mi++)
        #pragma unroll
        for (int n8 = 0; n8 < 4; n8++) {
            const float* c = C[mi * 4 + n8];
            int gm = m0 + wy * 32 + mi * 16 + g;
            int n  = n0 + wx * 32 + n8 * 8 + t * 2;
            float* o = out + (size_t)gm * DM + n;
            *(float2*)o = make_float2(c[0], c[1]);
            *(float2*)(o + 8 * DM) = make_float2(c[2], c[3]);
        }
}

// ---------------------------------------------------------------------------
extern "C" void kernel_launch(void* const* d_in, const int* in_sizes, int n_in,
                              void* d_out, int out_size)
{
    (void)in_sizes; (void)n_in; (void)out_size;
    // metadata order: x, Wk, Wq, Wv, Wo
    const float* x  = (const float*)d_in[0];
    const float* Wk = (const float*)d_in[1];
    const float* Wq = (const float*)d_in[2];
    const float* Wv = (const float*)d_in[3];
    const float* Wo = (const float*)d_in[4];
    float* out = (float*)d_out;

    cudaFuncSetAttribute(qkv_mma_kernel,
                         cudaFuncAttributeMaxDynamicSharedMemorySize, GEMM_SMEM);
    cudaFuncSetAttribute(out_mma_kernel,
                         cudaFuncAttributeMaxDynamicSharedMemorySize, GEMM_SMEM);
    cudaFuncSetAttribute(attn_mma_kernel,
                         cudaFuncAttributeMaxDynamicSharedMemorySize, ATT_SMEM);

    prep_x_kernel<<<(NB*NS*DM)/256, 256>>>(x);
    prep_w_kernel<<<(NH*3*DK*DM)/256, 256>>>(Wq, Wk, Wv);
    prep_wo_kernel<<<(DM*DM)/256, 256>>>(Wo);
    qkv_mma_kernel<<<dim3(32, NH, 3), 256, GEMM_SMEM>>>();
    attn_mma_kernel<<<dim3(NS/128, NB*NH), 256, ATT_SMEM>>>();
    out_mma_kernel<<<dim3(DM/64, (NB*NS)/128), 256, GEMM_SMEM>>>(out);
}

// round 17
// speedup vs baseline: 4.0918x; 1.0315x over previous
#include <cuda_runtime.h>
#include <cuda_bf16.h>
#include <math.h>
#include <stdint.h>

#define NB 2
#define NS 2048
#define DM 1024
#define DK 64
#define NH 16
#define LDT 40   // padded smem row stride (elems) for 32-wide GEMM tiles
#define ALD 72   // padded smem row stride (elems) for 64-wide attention tiles

typedef unsigned int u32;
typedef __nv_bfloat16 bf16;

// ---------------- scratch (__device__ globals; no allocs allowed) ----------
__device__ bf16 g_Qhi[NB*NH*NS*DK];  // Q pre-scaled by 1/8
__device__ bf16 g_Qlo[NB*NH*NS*DK];
__device__ bf16 g_Khi[NB*NH*NS*DK];
__device__ bf16 g_Klo[NB*NH*NS*DK];
__device__ bf16 g_Vhi[NB*NH*NS*DK];
__device__ bf16 g_Vlo[NB*NH*NS*DK];
__device__ bf16 g_Xhi[NB*NS*DM];
__device__ bf16 g_Xlo[NB*NS*DM];
__device__ bf16 g_Wthi[NH*3*DK*DM];   // [h][p*64+n][m]  (p: 0=Q,1=K,2=V)
__device__ bf16 g_Wtlo[NH*3*DK*DM];
__device__ bf16 g_Wohi[DM*DM];        // [mo][c] = Wo[c][mo]
__device__ bf16 g_Wolo[DM*DM];
__device__ bf16 g_Chi[NB*NS*NH*DK];   // ctx split, [b*NS+s][h*64+n]
__device__ bf16 g_Clo[NB*NS*NH*DK];

// ---------------- bf16 hi/lo split ----------------------------------------
__device__ __forceinline__ void split2(float x, bf16* hi, bf16* lo) {
    bf16 h = __float2bfloat16(x);
    *hi = h;
    *lo = __float2bfloat16(x - __bfloat162float(h));
}
__device__ __forceinline__ void pack_pair(float x, float y, u32& hi, u32& lo) {
    __nv_bfloat162 h = __floats2bfloat162_rn(x, y);
    hi = *(u32*)&h;
    float rx = x - __bfloat162float(h.x);
    float ry = y - __bfloat162float(h.y);
    __nv_bfloat162 l2 = __floats2bfloat162_rn(rx, ry);
    lo = *(u32*)&l2;
}

__global__ void prep_x_kernel(const float* __restrict__ x) {
    int i = blockIdx.x * 256 + threadIdx.x;
    split2(x[i], &g_Xhi[i], &g_Xlo[i]);
}
__global__ void prep_w_kernel(const float* __restrict__ Wq,
                              const float* __restrict__ Wk,
                              const float* __restrict__ Wv) {
    int i = blockIdx.x * 256 + threadIdx.x;           // NH*192*DM
    int m  = i & (DM - 1);
    int t  = i >> 10;
    int pn = t % 192;
    int h  = t / 192;
    int p  = pn >> 6, n = pn & 63;
    const float* W = (p == 0) ? Wq : ((p == 1) ? Wk : Wv);
    float v = W[(size_t)h * DM * DK + (size_t)m * DK + n];
    split2(v, &g_Wthi[i], &g_Wtlo[i]);
}
__global__ void prep_wo_kernel(const float* __restrict__ Wo) {
    int i = blockIdx.x * 256 + threadIdx.x;           // DM*DM, i = mo*1024 + c
    int c = i & (DM - 1), mo = i >> 10;
    split2(Wo[(size_t)c * DM + mo], &g_Wohi[i], &g_Wolo[i]);
}

// ---------------- PTX helpers -----------------------------------------------
__device__ __forceinline__ u32 smem_u32(const void* p) {
    u32 a;
    asm("{ .reg .u64 t; cvta.to.shared.u64 t, %1; cvt.u32.u64 %0, t; }" : "=r"(a) : "l"(p));
    return a;
}
__device__ __forceinline__ void cpa16(u32 dst, const void* src) {
    asm volatile("cp.async.ca.shared.global [%0], [%1], 16;" :: "r"(dst), "l"(src));
}
#define CP_COMMIT() asm volatile("cp.async.commit_group;" ::: "memory")
#define CP_WAIT(n)  asm volatile("cp.async.wait_group %0;" :: "n"(n) : "memory")
__device__ __forceinline__ void ldsm4(u32* r, u32 a) {
    asm volatile("ldmatrix.sync.aligned.m8n8.x4.shared.b16 {%0,%1,%2,%3}, [%4];"
                 : "=r"(r[0]), "=r"(r[1]), "=r"(r[2]), "=r"(r[3]) : "r"(a));
}
__device__ __forceinline__ void ldsm4t(u32* r, u32 a) {
    asm volatile("ldmatrix.sync.aligned.m8n8.x4.trans.shared.b16 {%0,%1,%2,%3}, [%4];"
                 : "=r"(r[0]), "=r"(r[1]), "=r"(r[2]), "=r"(r[3]) : "r"(a));
}
__device__ __forceinline__ void mma16816(float* c, const u32* a, const u32* b) {
    asm volatile(
        "mma.sync.aligned.m16n8k16.row.col.f32.bf16.bf16.f32 "
        "{%0,%1,%2,%3}, {%4,%5,%6,%7}, {%8,%9}, {%0,%1,%2,%3};"
        : "+f"(c[0]), "+f"(c[1]), "+f"(c[2]), "+f"(c[3])
        : "r"(a[0]), "r"(a[1]), "r"(a[2]), "r"(a[3]), "r"(b[0]), "r"(b[1]));
}

// ===========================================================================
// Merged QKV kernel: block 128x192 (all 3 projections), 512 threads.
// Warps 4m x 4n; warp tile 32x48. A tile loaded ONCE per CTA.
// ===========================================================================
#define Q_ST 51200u
#define Q_AH(s) ((s) * Q_ST)
#define Q_AL(s) (Q_AH(s) + 10240u)
#define Q_BH(s) (Q_AH(s) + 20480u)
#define Q_BL(s) (Q_AH(s) + 35840u)
#define QKV_SMEM 102400

__device__ __forceinline__ void qkv_fill(
    u32 sb, int s,
    const bf16* __restrict__ Ah, const bf16* __restrict__ Al,
    const bf16* __restrict__ Bh, const bf16* __restrict__ Bl,
    int kt, int tid)
{
    // A: 128 rows x 32 k, hi+lo = 1024 chunks
    #pragma unroll
    for (int e = 0; e < 2; e++) {
        int idx = tid + e * 512;
        int buf = idx >> 9, sub = idx & 511;
        int r = sub >> 2, c = sub & 3;
        cpa16(sb + (buf ? Q_AL(s) : Q_AH(s)) + (u32)(r * LDT + c * 8) * 2,
              (buf ? Al : Ah) + (size_t)r * DM + kt + c * 8);
    }
    // B: 192 rows x 32 k, hi+lo = 1536 chunks
    #pragma unroll
    for (int e = 0; e < 3; e++) {
        int idx = tid + e * 512;
        int buf = idx >= 768 ? 1 : 0;
        int sub = idx - buf * 768;
        int r = sub >> 2, c = sub & 3;
        cpa16(sb + (buf ? Q_BL(s) : Q_BH(s)) + (u32)(r * LDT + c * 8) * 2,
              (buf ? Bl : Bh) + (size_t)r * DM + kt + c * 8);
    }
}

__global__ void __launch_bounds__(512, 1) qkv_mma_kernel() {
    extern __shared__ __align__(16) char gsm[];
    u32 sb = smem_u32(gsm);

    const int tid = threadIdx.x, lane = tid & 31, wid = tid >> 5;
    const int wy = wid >> 2, wx = wid & 3;          // 4m x 4n
    const int quad = lane >> 3, qr = lane & 7;
    const int g = lane >> 2, t = lane & 3;
    const int a_row = (quad & 1) * 8 + qr, a_col = (quad >> 1) * 8;
    const int b_row = (quad >> 1) * 8 + qr, b_col = (quad & 1) * 8;

    const int m0 = blockIdx.x * 128;
    const int h  = blockIdx.y;

    const bf16* Ah = g_Xhi + (size_t)m0 * DM;
    const bf16* Al = g_Xlo + (size_t)m0 * DM;
    const bf16* Bh = g_Wthi + (size_t)h * 192 * DM;
    const bf16* Bl = g_Wtlo + (size_t)h * 192 * DM;

    float C[2][3][2][4];
    #pragma unroll
    for (int mi = 0; mi < 2; mi++)
        #pragma unroll
        for (int ng = 0; ng < 3; ng++)
            #pragma unroll
            for (int hf = 0; hf < 2; hf++)
                #pragma unroll
                for (int j = 0; j < 4; j++) C[mi][ng][hf][j] = 0.0f;

    qkv_fill(sb, 0, Ah, Al, Bh, Bl, 0, tid);
    CP_COMMIT();

    #pragma unroll 1
    for (int it = 0; it < DM / 32; it++) {
        int cur = it & 1;
        if (it + 1 < DM / 32) {
            qkv_fill(sb, cur ^ 1, Ah, Al, Bh, Bl, (it + 1) * 32, tid);
            CP_COMMIT();
            CP_WAIT(1);
        } else {
            CP_WAIT(0);
        }
        __syncthreads();

        const u32 aAh = sb + Q_AH(cur), aAl = sb + Q_AL(cur);
        const u32 aBh = sb + Q_BH(cur), aBl = sb + Q_BL(cur);
        #pragma unroll
        for (int k16 = 0; k16 < 2; k16++) {
            u32 Afh[2][4], Afl[2][4];
            #pragma unroll
            for (int mi = 0; mi < 2; mi++) {
                int row = wy * 32 + mi * 16 + a_row;
                u32 off = (u32)(row * LDT + k16 * 16 + a_col) * 2;
                ldsm4(Afh[mi], aAh + off);
                ldsm4(Afl[mi], aAl + off);
            }
            #pragma unroll
            for (int ng = 0; ng < 3; ng++) {
                int row = wx * 48 + ng * 16 + b_row;
                u32 off = (u32)(row * LDT + k16 * 16 + b_col) * 2;
                u32 Bfh[4], Bfl[4];
                ldsm4(Bfh, aBh + off);
                ldsm4(Bfl, aBl + off);
                #pragma unroll
                for (int mi = 0; mi < 2; mi++)
                    #pragma unroll
                    for (int hf = 0; hf < 2; hf++) {
                        float* c = C[mi][ng][hf];
                        mma16816(c, Afh[mi], &Bfh[hf * 2]);
                        mma16816(c, Afh[mi], &Bfl[hf * 2]);
                        mma16816(c, Afl[mi], &Bfh[hf * 2]);
                    }
            }
        }
        __syncthreads();
    }

    // epilogue: scatter to Q/K/V split buffers
    #pragma unroll
    for (int mi = 0; mi < 2; mi++) {
        int gm = m0 + wy * 32 + mi * 16 + g;
        int b = gm >> 11, s = gm & (NS - 1);
        #pragma unroll
        for (int ng = 0; ng < 3; ng++)
            #pragma unroll
            for (int hf = 0; hf < 2; hf++) {
                const float* c = C[mi][ng][hf];
                int nb = wx * 48 + ng * 16 + hf * 8 + t * 2;
                int p = nb >> 6, n = nb & 63;
                bf16 *dh, *dl;
                float sc;
                if (p == 0)      { dh = g_Qhi; dl = g_Qlo; sc = 0.125f; }
                else if (p == 1) { dh = g_Khi; dl = g_Klo; sc = 1.0f; }
                else             { dh = g_Vhi; dl = g_Vlo; sc = 1.0f; }
                size_t base = ((size_t)(b * NH + h) * NS + s) * DK + n;
                u32 hi, lo;
                pack_pair(c[0] * sc, c[1] * sc, hi, lo);
                *(u32*)(dh + base) = hi; *(u32*)(dl + base) = lo;
                pack_pair(c[2] * sc, c[3] * sc, hi, lo);
                *(u32*)(dh + base + 8 * DK) = hi; *(u32*)(dl + base + 8 * DK) = lo;
            }
    }
}

// ===========================================================================
// HMMA flash attention: 128 threads, 4 warps, warp tile 32 q-rows x 64 keys.
// K/V frags shared across both m-frags -> half the LDSM traffic per MMA.
// ===========================================================================
#define A_QH 0u
#define A_QL 18432u
#define A_KV(s)    (36864u + (s) * 36864u)
#define A_BUF(s,b) (A_KV(s) + (b) * 9216u)
#define ATT_SMEM 110592

__global__ void __launch_bounds__(128, 2) attn_mma_kernel() {
    extern __shared__ __align__(16) char asm_[];
    u32 sb = smem_u32(asm_);

    const int tid = threadIdx.x, lane = tid & 31, wid = tid >> 5;  // 4 warps
    const int bh = blockIdx.y, b = bh >> 4, h = bh & 15;
    const int m0 = blockIdx.x * 128;
    const int g = lane >> 2, t = lane & 3;
    const int quad = lane >> 3, qr = lane & 7;

    const bf16* gQh = g_Qhi + ((size_t)bh * NS + m0) * DK;
    const bf16* gQl = g_Qlo + ((size_t)bh * NS + m0) * DK;
    const bf16* gKh = g_Khi + (size_t)bh * NS * DK;
    const bf16* gKl = g_Klo + (size_t)bh * NS * DK;
    const bf16* gVh = g_Vhi + (size_t)bh * NS * DK;
    const bf16* gVl = g_Vlo + (size_t)bh * NS * DK;

    // Q tiles: 2048 chunks
    #pragma unroll
    for (int e = 0; e < 16; e++) {
        int idx = tid + e * 128;
        int buf = idx >> 10, sub = idx & 1023;
        int r = sub >> 3, c = sub & 7;
        cpa16(sb + (buf ? A_QL : A_QH) + (u32)(r * ALD + c * 8) * 2,
              (buf ? gQl : gQh) + (size_t)r * DK + c * 8);
    }
    // KV stage 0, tile 0: 2048 chunks
    #pragma unroll
    for (int e = 0; e < 16; e++) {
        int idx = tid + e * 128;
        int buf = idx >> 9, sub = idx & 511;
        int r = sub >> 3, c = sub & 7;
        const bf16* base = (buf == 0 ? gKh : buf == 1 ? gKl : buf == 2 ? gVh : gVl);
        cpa16(sb + A_BUF(0, buf) + (u32)(r * ALD + c * 8) * 2,
              base + (size_t)r * DK + c * 8);
    }
    CP_COMMIT();

    const int ar      = (quad & 1) * 8 + qr;   // within m-frag
    const int a_colb  = (quad >> 1) * 8;
    const int kb_row  = (quad >> 1) * 8 + qr;
    const int kb_colb = (quad & 1) * 8;
    const int vb_row  = (quad & 1) * 8 + qr;
    const int vb_colb = (quad >> 1) * 8;

    float O[2][8][4];
    #pragma unroll
    for (int mi = 0; mi < 2; mi++)
        #pragma unroll
        for (int i = 0; i < 8; i++)
            #pragma unroll
            for (int j = 0; j < 4; j++) O[mi][i][j] = 0.0f;
    float mrow[2][2] = {{-INFINITY, -INFINITY}, {-INFINITY, -INFINITY}};
    float lrow[2][2] = {{0.0f, 0.0f}, {0.0f, 0.0f}};

    #pragma unroll 1
    for (int tile = 0; tile < NS / 64; tile++) {
        int cur = tile & 1;
        if (tile + 1 < NS / 64) {
            #pragma unroll
            for (int e = 0; e < 16; e++) {
                int idx = tid + e * 128;
                int buf = idx >> 9, sub = idx & 511;
                int r = sub >> 3, c = sub & 7;
                const bf16* base = (buf == 0 ? gKh : buf == 1 ? gKl : buf == 2 ? gVh : gVl);
                cpa16(sb + A_BUF(cur ^ 1, buf) + (u32)(r * ALD + c * 8) * 2,
                      base + (size_t)((tile + 1) * 64 + r) * DK + c * 8);
            }
            CP_COMMIT();
            CP_WAIT(1);
        } else {
            CP_WAIT(0);
        }
        __syncthreads();

        const u32 aQh = sb + A_QH, aQl = sb + A_QL;
        const u32 aKh = sb + A_BUF(cur, 0), aKl = sb + A_BUF(cur, 1);
        const u32 aVh = sb + A_BUF(cur, 2), aVl = sb + A_BUF(cur, 3);

        // ---- scores S[32 x 64] per warp ----
        float S[2][8][4];
        #pragma unroll
        for (int mi = 0; mi < 2; mi++)
            #pragma unroll
            for (int i = 0; i < 8; i++)
                #pragma unroll
                for (int j = 0; j < 4; j++) S[mi][i][j] = 0.0f;

        #pragma unroll
        for (int k16 = 0; k16 < 4; k16++) {
            u32 qh[2][4], ql[2][4];
            #pragma unroll
            for (int mi = 0; mi < 2; mi++) {
                u32 qoff = (u32)((wid * 32 + mi * 16 + ar) * ALD + k16 * 16 + a_colb) * 2;
                ldsm4(qh[mi], aQh + qoff);
                ldsm4(ql[mi], aQl + qoff);
            }
            #pragma unroll
            for (int np = 0; np < 4; np++) {
                u32 koff = (u32)((np * 16 + kb_row) * ALD + k16 * 16 + kb_colb) * 2;
                u32 kh[4], kl[4];
                ldsm4(kh, aKh + koff);
                ldsm4(kl, aKl + koff);
                #pragma unroll
                for (int mi = 0; mi < 2; mi++)
                    #pragma unroll
                    for (int hf = 0; hf < 2; hf++) {
                        float* c = S[mi][np * 2 + hf];
                        mma16816(c, qh[mi], &kh[hf * 2]);
                        mma16816(c, qh[mi], &kl[hf * 2]);
                        mma16816(c, ql[mi], &kh[hf * 2]);
                    }
            }
        }

        // ---- online softmax per m-frag ----
        #pragma unroll
        for (int mi = 0; mi < 2; mi++) {
            float mx0 = S[mi][0][0], mx1 = S[mi][0][2];
            #pragma unroll
            for (int i = 0; i < 8; i++) {
                mx0 = fmaxf(mx0, fmaxf(S[mi][i][0], S[mi][i][1]));
                mx1 = fmaxf(mx1, fmaxf(S[mi][i][2], S[mi][i][3]));
            }
            mx0 = fmaxf(mx0, __shfl_xor_sync(0xffffffffu, mx0, 1));
            mx0 = fmaxf(mx0, __shfl_xor_sync(0xffffffffu, mx0, 2));
            mx1 = fmaxf(mx1, __shfl_xor_sync(0xffffffffu, mx1, 1));
            mx1 = fmaxf(mx1, __shfl_xor_sync(0xffffffffu, mx1, 2));
            float mn0 = fmaxf(mrow[mi][0], mx0), mn1 = fmaxf(mrow[mi][1], mx1);
            float c0 = __expf(mrow[mi][0] - mn0), c1 = __expf(mrow[mi][1] - mn1);
            mrow[mi][0] = mn0; mrow[mi][1] = mn1;
            float s0 = 0.0f, s1 = 0.0f;
            #pragma unroll
            for (int i = 0; i < 8; i++) {
                S[mi][i][0] = __expf(S[mi][i][0] - mn0); s0 += S[mi][i][0];
                S[mi][i][1] = __expf(S[mi][i][1] - mn0); s0 += S[mi][i][1];
                S[mi][i][2] = __expf(S[mi][i][2] - mn1); s1 += S[mi][i][2];
                S[mi][i][3] = __expf(S[mi][i][3] - mn1); s1 += S[mi][i][3];
                O[mi][i][0] *= c0; O[mi][i][1] *= c0;
                O[mi][i][2] *= c1; O[mi][i][3] *= c1;
            }
            s0 += __shfl_xor_sync(0xffffffffu, s0, 1);
            s0 += __shfl_xor_sync(0xffffffffu, s0, 2);
            s1 += __shfl_xor_sync(0xffffffffu, s1, 1);
            s1 += __shfl_xor_sync(0xffffffffu, s1, 2);
            lrow[mi][0] = lrow[mi][0] * c0 + s0;
            lrow[mi][1] = lrow[mi][1] * c1 + s1;
        }

        // ---- PV: O += P @ V (V frags shared across both m-frags) ----
        #pragma unroll
        for (int k16 = 0; k16 < 4; k16++) {
            u32 ph[2][4], pl[2][4];
            #pragma unroll
            for (int mi = 0; mi < 2; mi++) {
                pack_pair(S[mi][2*k16][0],   S[mi][2*k16][1],   ph[mi][0], pl[mi][0]);
                pack_pair(S[mi][2*k16][2],   S[mi][2*k16][3],   ph[mi][1], pl[mi][1]);
                pack_pair(S[mi][2*k16+1][0], S[mi][2*k16+1][1], ph[mi][2], pl[mi][2]);
                pack_pair(S[mi][2*k16+1][2], S[mi][2*k16+1][3], ph[mi][3], pl[mi][3]);
            }
            #pragma unroll
            for (int np = 0; np < 4; np++) {
                u32 voff = (u32)((k16 * 16 + vb_row) * ALD + np * 16 + vb_colb) * 2;
                u32 vh[4], vl[4];
                ldsm4t(vh, aVh + voff);
                ldsm4t(vl, aVl + voff);
                #pragma unroll
                for (int mi = 0; mi < 2; mi++)
                    #pragma unroll
                    for (int hf = 0; hf < 2; hf++) {
                        float* o = O[mi][np * 2 + hf];
                        mma16816(o, ph[mi], &vh[hf * 2]);
                        mma16816(o, ph[mi], &vl[hf * 2]);
                        mma16816(o, pl[mi], &vh[hf * 2]);
                    }
            }
        }
        __syncthreads();
    }

    // ---- epilogue: O/l -> split ctx ----
    #pragma unroll
    for (int mi = 0; mi < 2; mi++) {
        float inv0 = 1.0f / lrow[mi][0], inv1 = 1.0f / lrow[mi][1];
        int srow = m0 + wid * 32 + mi * 16 + g;
        #pragma unroll
        for (int n8 = 0; n8 < 8; n8++) {
            int n = h * 64 + n8 * 8 + t * 2;
            size_t r0 = (size_t)(b * NS + srow) * (NH * DK) + n;
            size_t r1 = r0 + (size_t)8 * NH * DK;
            u32 hi, lo;
            pack_pair(O[mi][n8][0] * inv0, O[mi][n8][1] * inv0, hi, lo);
            *(u32*)(g_Chi + r0) = hi; *(u32*)(g_Clo + r0) = lo;
            pack_pair(O[mi][n8][2] * inv1, O[mi][n8][3] * inv1, hi, lo);
            *(u32*)(g_Chi + r1) = hi; *(u32*)(g_Clo + r1) = lo;
        }
    }
}

// ===========================================================================
// Output projection (unchanged R15 core): block 128x64, 256 threads
// ===========================================================================
#define G_AH(s) ((s) * 30720u)
#define G_AL(s) (G_AH(s) + 10240u)
#define G_BH(s) (G_AH(s) + 20480u)
#define G_BL(s) (G_AH(s) + 25600u)
#define GEMM_SMEM 61440

__device__ __forceinline__ void gemm_fill(
    u32 sb, int s,
    const bf16* __restrict__ Agh, const bf16* __restrict__ Agl,
    const bf16* __restrict__ Bgh, const bf16* __restrict__ Bgl,
    int kt, int tid)
{
    #pragma unroll
    for (int e = 0; e < 2; e++) {
        int idx = tid + e * 256;
        int r = idx >> 2, c = idx & 3;
        u32 off = (u32)(r * LDT + c * 8) * 2;
        cpa16(sb + G_AH(s) + off, Agh + (size_t)r * DM + kt + c * 8);
        cpa16(sb + G_AL(s) + off, Agl + (size_t)r * DM + kt + c * 8);
    }
    {
        int r = tid >> 2, c = tid & 3;
        u32 off = (u32)(r * LDT + c * 8) * 2;
        cpa16(sb + G_BH(s) + off, Bgh + (size_t)r * DM + kt + c * 8);
        cpa16(sb + G_BL(s) + off, Bgl + (size_t)r * DM + kt + c * 8);
    }
}

__global__ void __launch_bounds__(256) out_mma_kernel(float* __restrict__ out) {
    extern __shared__ __align__(16) char gsm[];
    u32 sb = smem_u32(gsm);

    const int tid  = threadIdx.x;
    const int lane = tid & 31, wid = tid >> 5;
    const int wy = wid >> 1, wx = wid & 1;
    const int quad = lane >> 3, qr = lane & 7;
    const int a_row = (quad & 1) * 8 + qr, a_col = (quad >> 1) * 8;
    const int b_row = (quad >> 1) * 8 + qr, b_col = (quad & 1) * 8;
    const int g = lane >> 2, t = lane & 3;

    const int n0 = blockIdx.x * 64;
    const int m0 = blockIdx.y * 128;

    const bf16* Agh = g_Chi + (size_t)m0 * DM;
    const bf16* Agl = g_Clo + (size_t)m0 * DM;
    const bf16* Bgh = g_Wohi + (size_t)n0 * DM;
    const bf16* Bgl = g_Wolo + (size_t)n0 * DM;

    float C[8][4];
    #pragma unroll
    for (int i = 0; i < 8; i++)
        #pragma unroll
        for (int j = 0; j < 4; j++) C[i][j] = 0.0f;

    gemm_fill(sb, 0, Agh, Agl, Bgh, Bgl, 0, tid);
    CP_COMMIT();

    #pragma unroll 1
    for (int it = 0; it < DM / 32; it++) {
        int cur = it & 1;
        if (it + 1 < DM / 32) {
            gemm_fill(sb, cur ^ 1, Agh, Agl, Bgh, Bgl, (it + 1) * 32, tid);
            CP_COMMIT();
            CP_WAIT(1);
        } else {
            CP_WAIT(0);
        }
        __syncthreads();

        const u32 aAh = sb + G_AH(cur), aAl = sb + G_AL(cur);
        const u32 aBh = sb + G_BH(cur), aBl = sb + G_BL(cur);
        #pragma unroll
        for (int k16 = 0; k16 < 2; k16++) {
            u32 Afh[2][4], Afl[2][4], Bfh[2][4], Bfl[2][4];
            #pragma unroll
            for (int mi = 0; mi < 2; mi++) {
                int row = wy * 32 + mi * 16 + a_row;
                u32 off = (u32)(row * LDT + k16 * 16 + a_col) * 2;
                ldsm4(Afh[mi], aAh + off);
                ldsm4(Afl[mi], aAl + off);
            }
            #pragma unroll
            for (int ng = 0; ng < 2; ng++) {
                int row = wx * 32 + ng * 16 + b_row;
                u32 off = (u32)(row * LDT + k16 * 16 + b_col) * 2;
                ldsm4(Bfh[ng], aBh + off);
                ldsm4(Bfl[ng], aBl + off);
            }
            #pragma unroll
            for (int mi = 0; mi < 2; mi++)
                #pragma unroll
                for (int ng = 0; ng < 2; ng++)
                    #pragma unroll
                    for (int hf = 0; hf < 2; hf++) {
                        float* c = C[mi * 4 + ng * 2 + hf];
                        mma16816(c, Afh[mi], &Bfh[ng][hf * 2]);
                        mma16816(c, Afh[mi], &Bfl[ng][hf * 2]);
                        mma16816(c, Afl[mi], &Bfh[ng][hf * 2]);
                    }
        }
        __syncthreads();
    }

    #pragma unroll
    for (int mi = 0; mi < 2; mi++)
        #pragma unroll
        for (int n8 = 0; n8 < 4; n8++) {
            const float* c = C[mi * 4 + n8];
            int gm = m0 + wy * 32 + mi * 16 + g;
            int n  = n0 + wx * 32 + n8 * 8 + t * 2;
            float* o = out + (size_t)gm * DM + n;
            *(float2*)o = make_float2(c[0], c[1]);
            *(float2*)(o + 8 * DM) = make_float2(c[2], c[3]);
        }
}

// ---------------------------------------------------------------------------
extern "C" void kernel_launch(void* const* d_in, const int* in_sizes, int n_in,
                              void* d_out, int out_size)
{
    (void)in_sizes; (void)n_in; (void)out_size;
    // metadata order: x, Wk, Wq, Wv, Wo
    const float* x  = (const float*)d_in[0];
    const float* Wk = (const float*)d_in[1];
    const float* Wq = (const float*)d_in[2];
    const float* Wv = (const float*)d_in[3];
    const float* Wo = (const float*)d_in[4];
    float* out = (float*)d_out;

    cudaFuncSetAttribute(qkv_mma_kernel,
                         cudaFuncAttributeMaxDynamicSharedMemorySize, QKV_SMEM);
    cudaFuncSetAttribute(out_mma_kernel,
                         cudaFuncAttributeMaxDynamicSharedMemorySize, GEMM_SMEM);
    cudaFuncSetAttribute(attn_mma_kernel,
                         cudaFuncAttributeMaxDynamicSharedMemorySize, ATT_SMEM);

    prep_x_kernel<<<(NB*NS*DM)/256, 256>>>(x);
    prep_w_kernel<<<(NH*3*DK*DM)/256, 256>>>(Wq, Wk, Wv);
    prep_wo_kernel<<<(DM*DM)/256, 256>>>(Wo);
    qkv_mma_kernel<<<dim3(32, NH), 512, QKV_SMEM>>>();
    attn_mma_kernel<<<dim3(NS/128, NB*NH), 128, ATT_SMEM>>>();
    out_mma_kernel<<<dim3(DM/64, (NB*NS)/128), 256, GEMM_SMEM>>>(out);
}